// round 9
// baseline (speedup 1.0000x reference)
#include <cuda_runtime.h>
#include <cstddef>

#define BB 64
#define SS 256
#define DD 300
#define HH 512
#define GG 2048   // 4*H
#define KC 1024   // 2*H
#define NBLK 128u

typedef unsigned long long ull;

// ---------------- scratch (static device globals; no allocation) ------------
__device__ float g_xz[2][(size_t)BB * SS * GG];   // per-dir input projections
__device__ float g_hs0[2][(size_t)BB * SS * HH];  // layer-0 seq outputs (original t)
__device__ float g_hT[2][2][HH * BB];             // [dir][parity][h*BB + b]
__device__ float g_fc1[BB * 512];
__device__ float g_fc2[BB * 256];
__device__ unsigned g_bar;

__global__ void k_zero_bar() { g_bar = 0u; }

#define FMA2(d, a, b, c) \
    asm("fma.rn.f32x2 %0, %1, %2, %3;" : "=l"(d) : "l"(a), "l"(b), "l"(c))

// ---------------- input-projection GEMM (f32x2 packed) ----------------------
// MODE 0: A[r][k] = emb[text[r]][k],                    K = 300
// MODE 1: A[r][k] = k<H ? hs0_f[r][k] : hs0_b[r][k-H],  K = 1024
// B is staged duplicated as (b,b) pairs; accumulators pair over adjacent rows.
template<int MODE>
__global__ void k_gemm_xz(const int* __restrict__ text,
                          const float* __restrict__ emb,
                          const float* __restrict__ Wf,
                          const float* __restrict__ bf_,
                          const float* __restrict__ Wb,
                          const float* __restrict__ bb_) {
    const int K = (MODE == 0) ? DD : KC;
    const int dir = blockIdx.z;
    const float* __restrict__ W    = dir ? Wb  : Wf;
    const float* __restrict__ bias = dir ? bb_ : bf_;
    float* __restrict__ out = g_xz[dir];

    __shared__ __align__(16) float As[16][68];
    __shared__ __align__(16) ull  Bsd[16][66];   // (b,b) dup pairs

    const int r0 = blockIdx.x * 64;
    const int j0 = blockIdx.y * 64;
    const int tid = threadIdx.x;
    const int tx = tid & 15;   // 4-col group
    const int ty = tid >> 4;   // 4-row group

    ull acc[2][4];             // [row-pair][j]; pair = rows (ty*4+2ip, +1)
    #pragma unroll
    for (int ip = 0; ip < 2; ip++)
        #pragma unroll
        for (int j = 0; j < 4; j++) acc[ip][j] = 0ull;

    for (int k0 = 0; k0 < K; k0 += 16) {
        // load A tile: 64 rows x 16 k
        #pragma unroll
        for (int p = 0; p < 4; p++) {
            int kk = tid & 15;
            int rr = (tid >> 4) + p * 16;
            int k = k0 + kk;
            int r = r0 + rr;
            float v = 0.f;
            if (k < K) {
                if (MODE == 0) {
                    v = emb[(size_t)text[r] * DD + k];
                } else {
                    v = (k < HH) ? g_hs0[0][(size_t)r * HH + k]
                                 : g_hs0[1][(size_t)r * HH + (k - HH)];
                }
            }
            As[kk][rr] = v;
        }
        // load W tile duplicated: 16 k x 64 j
        #pragma unroll
        for (int p = 0; p < 4; p++) {
            int jj = tid & 63;
            int kk = (tid >> 6) + p * 4;
            int k = k0 + kk;
            float v = (k < K) ? W[(size_t)k * GG + j0 + jj] : 0.f;
            ull pr;
            asm("mov.b64 %0, {%1,%2};" : "=l"(pr) : "f"(v), "f"(v));
            Bsd[kk][jj] = pr;
        }
        __syncthreads();
        #pragma unroll
        for (int kk = 0; kk < 16; kk++) {
            ulonglong2 ap  = *(const ulonglong2*)&As[kk][ty * 4];
            ulonglong2 b01 = *(const ulonglong2*)&Bsd[kk][tx * 4];
            ulonglong2 b23 = *(const ulonglong2*)&Bsd[kk][tx * 4 + 2];
            FMA2(acc[0][0], ap.x, b01.x, acc[0][0]);
            FMA2(acc[1][0], ap.y, b01.x, acc[1][0]);
            FMA2(acc[0][1], ap.x, b01.y, acc[0][1]);
            FMA2(acc[1][1], ap.y, b01.y, acc[1][1]);
            FMA2(acc[0][2], ap.x, b23.x, acc[0][2]);
            FMA2(acc[1][2], ap.y, b23.x, acc[1][2]);
            FMA2(acc[0][3], ap.x, b23.y, acc[0][3]);
            FMA2(acc[1][3], ap.y, b23.y, acc[1][3]);
        }
        __syncthreads();
    }

    #pragma unroll
    for (int ip = 0; ip < 2; ip++) {
        #pragma unroll
        for (int j = 0; j < 4; j++) {
            float lo, hi;
            asm("mov.b64 {%0,%1}, %2;" : "=f"(lo), "=f"(hi) : "l"(acc[ip][j]));
            int c = j0 + tx * 4 + j;
            int r = r0 + ty * 4 + ip * 2;
            out[(size_t)r * GG + c]       = lo + bias[c];
            out[(size_t)(r + 1) * GG + c] = hi + bias[c];
        }
    }
}

// ---------------- persistent LSTM recurrence --------------------------------
// grid = (64, 2 dirs), block = 256 (2 warps/SMSP for latency hiding),
// 1 block/SM via 147456 B dynamic smem. Each block owns 8 h-columns of one
// direction; each thread handles 2 batches. U duplicated (u,u) in smem,
// layout [k][tx*4+g] so the 4 gate pairs load as 2x LDS.128.
template<bool STORE_HS>
__global__ void __launch_bounds__(256, 1) k_lstm_persist(
        const int* __restrict__ text,
        const float* __restrict__ Uf,
        const float* __restrict__ Ub) {
    extern __shared__ float sm[];
    ull*   Usd = (ull*)sm;            // [512][32] dup pairs (128KB), [k][tx*4+g]
    float* hsm = sm + 512 * 64;       // [64 k][64 b] tile (16KB)

    const int dir = blockIdx.y;
    const int h0  = blockIdx.x * 8;
    const float* __restrict__ U  = dir ? Ub : Uf;
    const float* __restrict__ xz = g_xz[dir];
    const int tid = threadIdx.x;
    const int tx  = tid & 7;     // h offset
    const int ty  = tid >> 3;    // 0..31
    const int b0  = ty * 2;      // 2 batches per thread
    const int hid = h0 + tx;

    // stage duplicated U slice: Usd[k*32 + tx*4 + g] = (u,u)
    for (int i = tid; i < 512 * 32; i += 256) {
        int k = i >> 5, c = i & 31, txx = c >> 2, g = c & 3;
        float u = U[(size_t)k * GG + g * HH + h0 + txx];
        ull pr;
        asm("mov.b64 %0, {%1,%2};" : "=l"(pr) : "f"(u), "f"(u));
        Usd[i] = pr;
    }

    // zero owned parity-0 h cells; c,h live in registers
    ((float2*)g_hT[dir][0])[(hid * BB + b0) >> 1] = make_float2(0.f, 0.f);
    float creg[2] = {0.f, 0.f};
    float hreg[2] = {0.f, 0.f};

    unsigned epoch = 0;

    // ---- init barrier (arrive, shadow = step-0 prefetch, wait) ----
    __syncthreads();
    if (tid == 0) { __threadfence(); atomicAdd(&g_bar, 1u); }
    ++epoch;

    float xzr[2][4];
    int msk[2];
    {
        int t = dir ? (SS - 1) : 0;
        #pragma unroll
        for (int ib = 0; ib < 2; ib++) {
            size_t r = (size_t)(b0 + ib) * SS + t;
            msk[ib] = text[r];
            const float* xp = xz + r * GG + hid;
            xzr[ib][0] = xp[0];
            xzr[ib][1] = xp[HH];
            xzr[ib][2] = xp[2 * HH];
            xzr[ib][3] = xp[3 * HH];
        }
    }
    if (tid == 0) {
        unsigned tgt = epoch * NBLK;
        while (*(volatile unsigned*)&g_bar < tgt) __nanosleep(32);
        __threadfence();
    }
    __syncthreads();

    for (int p = 0; p < SS; p++) {
        const int t = dir ? (SS - 1 - p) : p;
        const float* __restrict__ hprev = g_hT[dir][p & 1];

        ull acc[4];   // 4 gates, pair = batches (b0, b0+1)
        #pragma unroll
        for (int g = 0; g < 4; g++) acc[g] = 0ull;

        // prefetch h tile 0 into registers (L2-coherent loads)
        float4 pf[4];
        {
            const float4* src = (const float4*)hprev;
            #pragma unroll
            for (int i = 0; i < 4; i++) pf[i] = __ldcg(src + tid + 256 * i);
        }

        for (int kt = 0; kt < 8; kt++) {
            __syncthreads();
            #pragma unroll
            for (int i = 0; i < 4; i++) ((float4*)hsm)[tid + 256 * i] = pf[i];
            if (kt < 7) {
                const float4* nsrc = (const float4*)(hprev + (kt + 1) * 64 * BB);
                #pragma unroll
                for (int i = 0; i < 4; i++) pf[i] = __ldcg(nsrc + tid + 256 * i);
            }
            __syncthreads();

            const ull* ub = Usd + (size_t)kt * 64 * 32 + tx * 4;
            #pragma unroll 16
            for (int kk = 0; kk < 64; kk++) {
                ull hv = *(const ull*)&hsm[kk * 64 + b0];
                ulonglong2 u01 = *(const ulonglong2*)(ub + (size_t)kk * 32);
                ulonglong2 u23 = *(const ulonglong2*)(ub + (size_t)kk * 32 + 2);
                FMA2(acc[0], hv, u01.x, acc[0]);
                FMA2(acc[1], hv, u01.y, acc[1]);
                FMA2(acc[2], hv, u23.x, acc[2]);
                FMA2(acc[3], hv, u23.y, acc[3]);
            }
        }

        // unpack: (lo,hi) = batches (b0, b0+1)
        float zz[2][4];
        #pragma unroll
        for (int g = 0; g < 4; g++) {
            float lo, hi;
            asm("mov.b64 {%0,%1}, %2;" : "=f"(lo), "=f"(hi) : "l"(acc[g]));
            zz[0][g] = lo; zz[1][g] = hi;
        }

        #pragma unroll
        for (int ib = 0; ib < 2; ib++) {
            float zi = zz[ib][0] + xzr[ib][0];
            float zf = zz[ib][1] + xzr[ib][1];
            float zg = zz[ib][2] + xzr[ib][2];
            float zo = zz[ib][3] + xzr[ib][3];
            float ig = 1.f / (1.f + __expf(-zi));
            float fg = 1.f / (1.f + __expf(-zf));
            float gg = tanhf(zg);
            float og = 1.f / (1.f + __expf(-zo));
            float cn = fg * creg[ib] + ig * gg;
            float hn = og * tanhf(cn);
            bool m = (msk[ib] != 0);
            creg[ib] = m ? cn : creg[ib];
            hreg[ib] = m ? hn : hreg[ib];
        }

        ((float2*)g_hT[dir][(p + 1) & 1])[(hid * BB + b0) >> 1] =
            make_float2(hreg[0], hreg[1]);

        // ---- barrier: arrive, shadow work, wait ----
        __syncthreads();                       // all block's h stores issued
        if (tid == 0) { __threadfence(); atomicAdd(&g_bar, 1u); }
        ++epoch;

        if (STORE_HS) {
            #pragma unroll
            for (int ib = 0; ib < 2; ib++)
                g_hs0[dir][((size_t)(b0 + ib) * SS + t) * HH + hid] = hreg[ib];
        }
        if (p + 1 < SS) {
            int t2 = dir ? (SS - 2 - p) : (p + 1);
            #pragma unroll
            for (int ib = 0; ib < 2; ib++) {
                size_t r = (size_t)(b0 + ib) * SS + t2;
                msk[ib] = text[r];
                const float* xp = xz + r * GG + hid;
                xzr[ib][0] = xp[0];
                xzr[ib][1] = xp[HH];
                xzr[ib][2] = xp[2 * HH];
                xzr[ib][3] = xp[3 * HH];
            }
        }
        if (tid == 0) {
            unsigned tgt = epoch * NBLK;
            while (*(volatile unsigned*)&g_bar < tgt) __nanosleep(32);
            __threadfence();
        }
        __syncthreads();
    }
}

// ---------------- dense head ------------------------------------------------
__global__ void k_dense0(const float* __restrict__ w, const float* __restrict__ bia) {
    int gw = (blockIdx.x * blockDim.x + threadIdx.x) >> 5;
    int lane = threadIdx.x & 31;
    if (gw >= BB * 512) return;
    int b = gw >> 9, j = gw & 511;
    float s = 0.f;
    for (int k = lane; k < KC; k += 32) {
        float a = (k < HH) ? g_hT[0][0][k * BB + b]
                           : g_hT[1][0][(k - HH) * BB + b];
        s += a * w[(size_t)k * 512 + j];
    }
    #pragma unroll
    for (int o = 16; o; o >>= 1) s += __shfl_xor_sync(0xffffffffu, s, o);
    if (!lane) {
        s += bia[j];
        g_fc1[b * 512 + j] = (s >= 0.f) ? s : 0.2f * s;
    }
}

__global__ void k_dense1(const float* __restrict__ w, const float* __restrict__ bia) {
    int gw = (blockIdx.x * blockDim.x + threadIdx.x) >> 5;
    int lane = threadIdx.x & 31;
    if (gw >= BB * 256) return;
    int b = gw >> 8, j = gw & 255;
    float s = 0.f;
    for (int k = lane; k < 512; k += 32)
        s += g_fc1[b * 512 + k] * w[(size_t)k * 256 + j];
    #pragma unroll
    for (int o = 16; o; o >>= 1) s += __shfl_xor_sync(0xffffffffu, s, o);
    if (!lane) {
        s += bia[j];
        g_fc2[b * 256 + j] = (s >= 0.f) ? s : 0.2f * s;
    }
}

__global__ void k_dense2(const float* __restrict__ w, const float* __restrict__ bia,
                         float* __restrict__ out) {
    int b = blockIdx.x;
    int lane = threadIdx.x;
    float s = 0.f;
    for (int k = lane; k < 256; k += 32)
        s += g_fc2[b * 256 + k] * w[k];
    #pragma unroll
    for (int o = 16; o; o >>= 1) s += __shfl_xor_sync(0xffffffffu, s, o);
    if (!lane) out[b] = s + bia[0];
}

// ---------------- launch ----------------------------------------------------
extern "C" void kernel_launch(void* const* d_in, const int* in_sizes, int n_in,
                              void* d_out, int out_size) {
    const int*   text = (const int*)  d_in[0];
    const float* emb  = (const float*)d_in[1];
    const float* W0f  = (const float*)d_in[2];
    const float* U0f  = (const float*)d_in[3];
    const float* b0f  = (const float*)d_in[4];
    const float* W0b  = (const float*)d_in[5];
    const float* U0b  = (const float*)d_in[6];
    const float* b0b  = (const float*)d_in[7];
    const float* W1f  = (const float*)d_in[8];
    const float* U1f  = (const float*)d_in[9];
    const float* b1f  = (const float*)d_in[10];
    const float* W1b  = (const float*)d_in[11];
    const float* U1b  = (const float*)d_in[12];
    const float* b1b  = (const float*)d_in[13];
    const float* d0w  = (const float*)d_in[14];
    const float* d0b  = (const float*)d_in[15];
    const float* d1w  = (const float*)d_in[16];
    const float* d1b  = (const float*)d_in[17];
    const float* d2w  = (const float*)d_in[18];
    const float* d2b  = (const float*)d_in[19];
    float* out = (float*)d_out;

    const int smemsz = (512 * 64 + 64 * 64) * 4;  // 147456 B (proven-safe)
    cudaFuncSetAttribute(k_lstm_persist<true>,
                         cudaFuncAttributeMaxDynamicSharedMemorySize, smemsz);
    cudaFuncSetAttribute(k_lstm_persist<false>,
                         cudaFuncAttributeMaxDynamicSharedMemorySize, smemsz);

    // ---- layer 0 ----
    k_zero_bar<<<1, 1>>>();
    k_gemm_xz<0><<<dim3(BB * SS / 64, GG / 64, 2), 256>>>(text, emb, W0f, b0f, W0b, b0b);
    k_lstm_persist<true><<<dim3(64, 2), 256, smemsz>>>(text, U0f, U0b);

    // ---- layer 1 ----
    k_zero_bar<<<1, 1>>>();
    k_gemm_xz<1><<<dim3(BB * SS / 64, GG / 64, 2), 256>>>(text, emb, W1f, b1f, W1b, b1b);
    k_lstm_persist<false><<<dim3(64, 2), 256, smemsz>>>(text, U1f, U1b);

    // ---- dense head ----
    k_dense0<<<(BB * 512 * 32) / 256, 256>>>(d0w, d0b);
    k_dense1<<<(BB * 256 * 32) / 256, 256>>>(d1w, d1b);
    k_dense2<<<BB, 32>>>(d2w, d2b, out);
}

// round 10
// speedup vs baseline: 1.6008x; 1.6008x over previous
#include <cuda_runtime.h>
#include <cstddef>

#define BB 64
#define SS 256
#define DD 300
#define HH 512
#define GG 2048   // 4*H
#define KC 1024   // 2*H
#define NDIRBLK 64u   // blocks per direction (each dir has its own barrier)

typedef unsigned long long ull;

// ---------------- scratch (static device globals; no allocation) ------------
__device__ float g_xz[2][(size_t)BB * SS * GG];   // per-dir input projections
__device__ float g_hs0[2][(size_t)BB * SS * HH];  // layer-0 seq outputs (original t)
__device__ float g_hT[2][2][HH * BB];             // [dir][parity][h*BB + b]
__device__ float g_fc1[BB * 512];
__device__ float g_fc2[BB * 256];
__device__ __align__(128) unsigned g_barA[64];    // [0]=dir0, [32]=dir1 (128B apart)

__global__ void k_zero_bar() { g_barA[0] = 0u; g_barA[32] = 0u; }

#define FMA2(d, a, b, c) \
    asm("fma.rn.f32x2 %0, %1, %2, %3;" : "=l"(d) : "l"(a), "l"(b), "l"(c))

// ---------------- input-projection GEMM (f32x2 packed) ----------------------
// MODE 0: A[r][k] = emb[text[r]][k],                    K = 300
// MODE 1: A[r][k] = k<H ? hs0_f[r][k] : hs0_b[r][k-H],  K = 1024
template<int MODE>
__global__ void k_gemm_xz(const int* __restrict__ text,
                          const float* __restrict__ emb,
                          const float* __restrict__ Wf,
                          const float* __restrict__ bf_,
                          const float* __restrict__ Wb,
                          const float* __restrict__ bb_) {
    const int K = (MODE == 0) ? DD : KC;
    const int dir = blockIdx.z;
    const float* __restrict__ W    = dir ? Wb  : Wf;
    const float* __restrict__ bias = dir ? bb_ : bf_;
    float* __restrict__ out = g_xz[dir];

    __shared__ __align__(16) float As[16][68];
    __shared__ __align__(16) ull  Bsd[16][66];   // (b,b) dup pairs

    const int r0 = blockIdx.x * 64;
    const int j0 = blockIdx.y * 64;
    const int tid = threadIdx.x;
    const int tx = tid & 15;   // 4-col group
    const int ty = tid >> 4;   // 4-row group

    ull acc[2][4];             // [row-pair][j]
    #pragma unroll
    for (int ip = 0; ip < 2; ip++)
        #pragma unroll
        for (int j = 0; j < 4; j++) acc[ip][j] = 0ull;

    for (int k0 = 0; k0 < K; k0 += 16) {
        #pragma unroll
        for (int p = 0; p < 4; p++) {
            int kk = tid & 15;
            int rr = (tid >> 4) + p * 16;
            int k = k0 + kk;
            int r = r0 + rr;
            float v = 0.f;
            if (k < K) {
                if (MODE == 0) {
                    v = emb[(size_t)text[r] * DD + k];
                } else {
                    v = (k < HH) ? g_hs0[0][(size_t)r * HH + k]
                                 : g_hs0[1][(size_t)r * HH + (k - HH)];
                }
            }
            As[kk][rr] = v;
        }
        #pragma unroll
        for (int p = 0; p < 4; p++) {
            int jj = tid & 63;
            int kk = (tid >> 6) + p * 4;
            int k = k0 + kk;
            float v = (k < K) ? W[(size_t)k * GG + j0 + jj] : 0.f;
            ull pr;
            asm("mov.b64 %0, {%1,%2};" : "=l"(pr) : "f"(v), "f"(v));
            Bsd[kk][jj] = pr;
        }
        __syncthreads();
        #pragma unroll
        for (int kk = 0; kk < 16; kk++) {
            ulonglong2 ap  = *(const ulonglong2*)&As[kk][ty * 4];
            ulonglong2 b01 = *(const ulonglong2*)&Bsd[kk][tx * 4];
            ulonglong2 b23 = *(const ulonglong2*)&Bsd[kk][tx * 4 + 2];
            FMA2(acc[0][0], ap.x, b01.x, acc[0][0]);
            FMA2(acc[1][0], ap.y, b01.x, acc[1][0]);
            FMA2(acc[0][1], ap.x, b01.y, acc[0][1]);
            FMA2(acc[1][1], ap.y, b01.y, acc[1][1]);
            FMA2(acc[0][2], ap.x, b23.x, acc[0][2]);
            FMA2(acc[1][2], ap.y, b23.x, acc[1][2]);
            FMA2(acc[0][3], ap.x, b23.y, acc[0][3]);
            FMA2(acc[1][3], ap.y, b23.y, acc[1][3]);
        }
        __syncthreads();
    }

    #pragma unroll
    for (int ip = 0; ip < 2; ip++) {
        #pragma unroll
        for (int j = 0; j < 4; j++) {
            float lo, hi;
            asm("mov.b64 {%0,%1}, %2;" : "=f"(lo), "=f"(hi) : "l"(acc[ip][j]));
            int c = j0 + tx * 4 + j;
            int r = r0 + ty * 4 + ip * 2;
            out[(size_t)r * GG + c]       = lo + bias[c];
            out[(size_t)(r + 1) * GG + c] = hi + bias[c];
        }
    }
}

// ---------------- persistent LSTM recurrence (R7 config, 128 thr) -----------
// grid = (64, 2 dirs), block = 128, 1 block/SM (147456 B dynamic smem).
// Per-direction barrier (64 participants), tight volatile spin (no nanosleep).
template<bool STORE_HS>
__global__ void __launch_bounds__(128, 1) k_lstm_persist(
        const int* __restrict__ text,
        const float* __restrict__ Uf,
        const float* __restrict__ Ub) {
    extern __shared__ float sm[];
    ull*   Usd = (ull*)sm;            // [512][32] dup pairs (128KB), [k][g*8+h]
    float* hsm = sm + 512 * 64;       // [64 k][64 b] tile (16KB)

    const int dir = blockIdx.y;
    const int h0  = blockIdx.x * 8;
    const float* __restrict__ U  = dir ? Ub : Uf;
    const float* __restrict__ xz = g_xz[dir];
    unsigned* ctr = &g_barA[dir * 32];
    const int tid = threadIdx.x;
    const int tx  = tid & 7;     // h offset
    const int ty  = tid >> 3;    // batch group
    const int b0  = ty * 4;
    const int hid = h0 + tx;

    // stage duplicated U slice: Usd[k][g*8+h] = (u,u)
    for (int i = tid; i < 512 * 32; i += 128) {
        int k = i >> 5, c = i & 31, g = c >> 3, hh = c & 7;
        float u = U[(size_t)k * GG + g * HH + h0 + hh];
        ull pr;
        asm("mov.b64 %0, {%1,%2};" : "=l"(pr) : "f"(u), "f"(u));
        Usd[i] = pr;
    }

    // zero owned parity-0 h cells; c,h live in registers
    __stcg((float4*)&g_hT[dir][0][hid * BB + b0], make_float4(0.f, 0.f, 0.f, 0.f));
    float creg[4] = {0.f, 0.f, 0.f, 0.f};
    float hreg[4] = {0.f, 0.f, 0.f, 0.f};

    unsigned epoch = 0;

    // ---- init barrier (arrive, shadow = step-0 prefetch, wait) ----
    __syncthreads();
    if (tid == 0) { __threadfence(); atomicAdd(ctr, 1u); }
    ++epoch;

    float xzr[4][4];
    int msk[4];
    {
        int t = dir ? (SS - 1) : 0;
        #pragma unroll
        for (int ib = 0; ib < 4; ib++) {
            size_t r = (size_t)(b0 + ib) * SS + t;
            msk[ib] = text[r];
            const float* xp = xz + r * GG + hid;
            xzr[ib][0] = xp[0];
            xzr[ib][1] = xp[HH];
            xzr[ib][2] = xp[2 * HH];
            xzr[ib][3] = xp[3 * HH];
        }
    }
    if (tid == 0) {
        unsigned tgt = epoch * NDIRBLK;
        while (*(volatile unsigned*)ctr < tgt) {}
        __threadfence();
    }
    __syncthreads();

    for (int p = 0; p < SS; p++) {
        const int t = dir ? (SS - 1 - p) : p;
        const float* __restrict__ hprev = g_hT[dir][p & 1];

        ull acc[2][4];
        #pragma unroll
        for (int q = 0; q < 2; q++)
            #pragma unroll
            for (int g = 0; g < 4; g++) acc[q][g] = 0ull;

        // prefetch h tile 0 into registers (L2-coherent loads)
        float4 pf[8];
        {
            const float4* src = (const float4*)hprev;
            #pragma unroll
            for (int i = 0; i < 8; i++) pf[i] = __ldcg(src + tid + 128 * i);
        }

        for (int k0 = 0; k0 < HH; k0 += 64) {
            __syncthreads();
            #pragma unroll
            for (int i = 0; i < 8; i++) ((float4*)hsm)[tid + 128 * i] = pf[i];
            if (k0 + 64 < HH) {
                const float4* nsrc = (const float4*)(hprev + (k0 + 64) * BB);
                #pragma unroll
                for (int i = 0; i < 8; i++) pf[i] = __ldcg(nsrc + tid + 128 * i);
            }
            __syncthreads();

            const ull* ub = Usd + (size_t)k0 * 32 + tx;
            #pragma unroll 16
            for (int kk = 0; kk < 64; kk++) {
                ulonglong2 hv = *(const ulonglong2*)&hsm[kk * 64 + b0];
                const ull* up = ub + (size_t)kk * 32;
                ull u0 = up[0], u1 = up[8], u2 = up[16], u3 = up[24];
                FMA2(acc[0][0], hv.x, u0, acc[0][0]);
                FMA2(acc[1][0], hv.y, u0, acc[1][0]);
                FMA2(acc[0][1], hv.x, u1, acc[0][1]);
                FMA2(acc[1][1], hv.y, u1, acc[1][1]);
                FMA2(acc[0][2], hv.x, u2, acc[0][2]);
                FMA2(acc[1][2], hv.y, u2, acc[1][2]);
                FMA2(acc[0][3], hv.x, u3, acc[0][3]);
                FMA2(acc[1][3], hv.y, u3, acc[1][3]);
            }
        }

        // unpack accumulators: pair0=(b0,b0+1), pair1=(b0+2,b0+3)
        float zz[4][4];
        #pragma unroll
        for (int g = 0; g < 4; g++) {
            float lo, hi;
            asm("mov.b64 {%0,%1}, %2;" : "=f"(lo), "=f"(hi) : "l"(acc[0][g]));
            zz[0][g] = lo; zz[1][g] = hi;
            asm("mov.b64 {%0,%1}, %2;" : "=f"(lo), "=f"(hi) : "l"(acc[1][g]));
            zz[2][g] = lo; zz[3][g] = hi;
        }

        #pragma unroll
        for (int ib = 0; ib < 4; ib++) {
            float zi = zz[ib][0] + xzr[ib][0];
            float zf = zz[ib][1] + xzr[ib][1];
            float zg = zz[ib][2] + xzr[ib][2];
            float zo = zz[ib][3] + xzr[ib][3];
            float ig = 1.f / (1.f + __expf(-zi));
            float fg = 1.f / (1.f + __expf(-zf));
            float gg = tanhf(zg);
            float og = 1.f / (1.f + __expf(-zo));
            float cn = fg * creg[ib] + ig * gg;
            float hn = og * tanhf(cn);
            bool m = (msk[ib] != 0);
            creg[ib] = m ? cn : creg[ib];
            hreg[ib] = m ? hn : hreg[ib];
        }

        __stcg((float4*)&g_hT[dir][(p + 1) & 1][hid * BB + b0],
               make_float4(hreg[0], hreg[1], hreg[2], hreg[3]));

        // ---- barrier: arrive, shadow work, wait ----
        __syncthreads();                       // all block's h stores issued
        if (tid == 0) { __threadfence(); atomicAdd(ctr, 1u); }
        ++epoch;

        if (STORE_HS) {
            #pragma unroll
            for (int ib = 0; ib < 4; ib++)
                g_hs0[dir][((size_t)(b0 + ib) * SS + t) * HH + hid] = hreg[ib];
        }
        if (p + 1 < SS) {
            int t2 = dir ? (SS - 2 - p) : (p + 1);
            #pragma unroll
            for (int ib = 0; ib < 4; ib++) {
                size_t r = (size_t)(b0 + ib) * SS + t2;
                msk[ib] = text[r];
                const float* xp = xz + r * GG + hid;
                xzr[ib][0] = xp[0];
                xzr[ib][1] = xp[HH];
                xzr[ib][2] = xp[2 * HH];
                xzr[ib][3] = xp[3 * HH];
            }
        }
        if (tid == 0) {
            unsigned tgt = epoch * NDIRBLK;
            while (*(volatile unsigned*)ctr < tgt) {}
            __threadfence();
        }
        __syncthreads();
    }
}

// ---------------- dense head ------------------------------------------------
__global__ void k_dense0(const float* __restrict__ w, const float* __restrict__ bia) {
    int gw = (blockIdx.x * blockDim.x + threadIdx.x) >> 5;
    int lane = threadIdx.x & 31;
    if (gw >= BB * 512) return;
    int b = gw >> 9, j = gw & 511;
    float s = 0.f;
    for (int k = lane; k < KC; k += 32) {
        float a = (k < HH) ? g_hT[0][0][k * BB + b]
                           : g_hT[1][0][(k - HH) * BB + b];
        s += a * w[(size_t)k * 512 + j];
    }
    #pragma unroll
    for (int o = 16; o; o >>= 1) s += __shfl_xor_sync(0xffffffffu, s, o);
    if (!lane) {
        s += bia[j];
        g_fc1[b * 512 + j] = (s >= 0.f) ? s : 0.2f * s;
    }
}

__global__ void k_dense1(const float* __restrict__ w, const float* __restrict__ bia) {
    int gw = (blockIdx.x * blockDim.x + threadIdx.x) >> 5;
    int lane = threadIdx.x & 31;
    if (gw >= BB * 256) return;
    int b = gw >> 8, j = gw & 255;
    float s = 0.f;
    for (int k = lane; k < 512; k += 32)
        s += g_fc1[b * 512 + k] * w[(size_t)k * 256 + j];
    #pragma unroll
    for (int o = 16; o; o >>= 1) s += __shfl_xor_sync(0xffffffffu, s, o);
    if (!lane) {
        s += bia[j];
        g_fc2[b * 256 + j] = (s >= 0.f) ? s : 0.2f * s;
    }
}

__global__ void k_dense2(const float* __restrict__ w, const float* __restrict__ bia,
                         float* __restrict__ out) {
    int b = blockIdx.x;
    int lane = threadIdx.x;
    float s = 0.f;
    for (int k = lane; k < 256; k += 32)
        s += g_fc2[b * 256 + k] * w[k];
    #pragma unroll
    for (int o = 16; o; o >>= 1) s += __shfl_xor_sync(0xffffffffu, s, o);
    if (!lane) out[b] = s + bia[0];
}

// ---------------- launch ----------------------------------------------------
extern "C" void kernel_launch(void* const* d_in, const int* in_sizes, int n_in,
                              void* d_out, int out_size) {
    const int*   text = (const int*)  d_in[0];
    const float* emb  = (const float*)d_in[1];
    const float* W0f  = (const float*)d_in[2];
    const float* U0f  = (const float*)d_in[3];
    const float* b0f  = (const float*)d_in[4];
    const float* W0b  = (const float*)d_in[5];
    const float* U0b  = (const float*)d_in[6];
    const float* b0b  = (const float*)d_in[7];
    const float* W1f  = (const float*)d_in[8];
    const float* U1f  = (const float*)d_in[9];
    const float* b1f  = (const float*)d_in[10];
    const float* W1b  = (const float*)d_in[11];
    const float* U1b  = (const float*)d_in[12];
    const float* b1b  = (const float*)d_in[13];
    const float* d0w  = (const float*)d_in[14];
    const float* d0b  = (const float*)d_in[15];
    const float* d1w  = (const float*)d_in[16];
    const float* d1b  = (const float*)d_in[17];
    const float* d2w  = (const float*)d_in[18];
    const float* d2b  = (const float*)d_in[19];
    float* out = (float*)d_out;

    const int smemsz = (512 * 64 + 64 * 64) * 4;  // 147456 B (proven-safe)
    cudaFuncSetAttribute(k_lstm_persist<true>,
                         cudaFuncAttributeMaxDynamicSharedMemorySize, smemsz);
    cudaFuncSetAttribute(k_lstm_persist<false>,
                         cudaFuncAttributeMaxDynamicSharedMemorySize, smemsz);

    // ---- layer 0 ----  (persist<true> placed at 0-based launch index 3,
    //                     the slot ncu has captured in every round so far)
    k_zero_bar<<<1, 1>>>();                                                  // 0
    k_gemm_xz<0><<<dim3(BB * SS / 64, GG / 64, 2), 256>>>(text, emb,
                                                          W0f, b0f, W0b, b0b); // 1
    k_zero_bar<<<1, 1>>>();                                                  // 2 (idempotent)
    k_lstm_persist<true><<<dim3(64, 2), 128, smemsz>>>(text, U0f, U0b);      // 3

    // ---- layer 1 ----
    k_gemm_xz<1><<<dim3(BB * SS / 64, GG / 64, 2), 256>>>(text, emb,
                                                          W1f, b1f, W1b, b1b); // 4
    k_zero_bar<<<1, 1>>>();                                                  // 5
    k_lstm_persist<false><<<dim3(64, 2), 128, smemsz>>>(text, U1f, U1b);     // 6

    // ---- dense head ----
    k_dense0<<<(BB * 512 * 32) / 256, 256>>>(d0w, d0b);
    k_dense1<<<(BB * 256 * 32) / 256, 256>>>(d1w, d1b);
    k_dense2<<<BB, 32>>>(d2w, d2b, out);
}

// round 14
// speedup vs baseline: 3.1149x; 1.9458x over previous
#include <cuda_runtime.h>
#include <cuda_bf16.h>
#include <cstdint>
#include <cstddef>

#define BB 64
#define SS 256
#define DD 300
#define HH 512
#define GG 2048   // 4*H
#define KC 1024   // 2*H
#define NBLK 128u
#define KP0 320   // layer0 K padded (300 -> 320)
#define KP1 1024  // layer1 K

typedef unsigned long long ull;
typedef __nv_bfloat16 bf16;

// ---------------- scratch (static device globals; no allocation) ------------
__device__ float g_xz[2][(size_t)BB * SS * GG];   // per-dir input projections
__device__ float g_hs0[2][(size_t)BB * SS * HH];  // layer-0 seq outputs (original t)
__device__ float g_hT[2][2][HH * BB];             // [dir][parity][h*BB + b]
__device__ float g_fc1[BB * 512];
__device__ float g_fc2[BB * 256];
__device__ unsigned g_bar;
// bf16 split buffers
__device__ bf16 g_a0h[(size_t)BB * SS * KP0];
__device__ bf16 g_a0l[(size_t)BB * SS * KP0];
__device__ bf16 g_a1h[(size_t)BB * SS * KP1];
__device__ bf16 g_a1l[(size_t)BB * SS * KP1];
__device__ bf16 g_w0h[(size_t)2 * GG * KP0];  // [dir][j][k] transposed
__device__ bf16 g_w0l[(size_t)2 * GG * KP0];
__device__ bf16 g_w1h[(size_t)2 * GG * KP1];
__device__ bf16 g_w1l[(size_t)2 * GG * KP1];

__global__ void k_zero_bar() { g_bar = 0u; }

#define FMA2(d, a, b, c) \
    asm("fma.rn.f32x2 %0, %1, %2, %3;" : "=l"(d) : "l"(a), "l"(b), "l"(c))

// m16n8k16 bf16 mma (sm_80+ feature; compiles for plain sm_103 target)
__device__ __forceinline__ void mma_bf16(float* d, const unsigned* a, const unsigned* b) {
    asm("mma.sync.aligned.m16n8k16.row.col.f32.bf16.bf16.f32 "
        "{%0,%1,%2,%3}, {%4,%5,%6,%7}, {%8,%9}, {%0,%1,%2,%3};"
        : "+f"(d[0]), "+f"(d[1]), "+f"(d[2]), "+f"(d[3])
        : "r"(a[0]), "r"(a[1]), "r"(a[2]), "r"(a[3]), "r"(b[0]), "r"(b[1]));
}

// ---------------- split kernels (fp32 -> bf16 hi/lo) -------------------------
__global__ void k_split_a0(const int* __restrict__ text,
                           const float* __restrict__ emb) {
    size_t i = (size_t)blockIdx.x * 256 + threadIdx.x;
    if (i >= (size_t)BB * SS * KP0) return;
    int k = (int)(i % KP0);
    size_t r = i / KP0;
    float v = (k < DD) ? emb[(size_t)text[r] * DD + k] : 0.f;
    bf16 h = __float2bfloat16(v);
    g_a0h[i] = h;
    g_a0l[i] = __float2bfloat16(v - __bfloat162float(h));
}

__global__ void k_split_a1() {
    size_t i = (size_t)blockIdx.x * 256 + threadIdx.x;
    if (i >= (size_t)BB * SS * KP1) return;
    int k = (int)(i & (KP1 - 1));
    size_t r = i >> 10;
    float v = (k < HH) ? g_hs0[0][r * HH + k] : g_hs0[1][r * HH + (k - HH)];
    bf16 h = __float2bfloat16(v);
    g_a1h[i] = h;
    g_a1l[i] = __float2bfloat16(v - __bfloat162float(h));
}

// W [K][2048] (per dir) -> transposed bf16 hi/lo [dir][2048][Kpad], zero-padded.
template<int LAYER>
__global__ void k_split_w(const float* __restrict__ Wf,
                          const float* __restrict__ Wb) {
    constexpr int K    = LAYER ? KC : DD;
    constexpr int Kpad = LAYER ? KP1 : KP0;
    bf16* __restrict__ hiT = LAYER ? g_w1h : g_w0h;   // device-side refs
    bf16* __restrict__ loT = LAYER ? g_w1l : g_w0l;
    size_t i = (size_t)blockIdx.x * 256 + threadIdx.x;
    if (i >= (size_t)2 * GG * Kpad) return;
    int k = (int)(i % Kpad);
    size_t jd = i / Kpad;
    int j = (int)(jd % GG);
    int d = (int)(jd / GG);
    float v = (k < K) ? (d ? Wb : Wf)[(size_t)k * GG + j] : 0.f;
    bf16 h = __float2bfloat16(v);
    hiT[i] = h;
    loT[i] = __float2bfloat16(v - __bfloat162float(h));
}

// ---------------- mma.sync bf16 split GEMM ----------------------------------
// out[r][j] = sum_k A[r][k]*W[k][j] + bias[j]  via Ah*Wh + Ah*Wl + Al*Wh.
// Block: 256 thr = 8 warps (2 M x 4 N), tile M=64 x N=256, K-chunks of 64.
// Smem rows padded to 72 bf16 (144B) -> conflict-free fragment loads.
// NOTE: split buffers referenced as device globals INSIDE the kernel —
// passing __device__ arrays as host-side kernel args reads the zero host
// shadow via ATS (the R13 bug).
#define AST 72
#define GEMM_SMEM ((2 * 64 * AST + 2 * 256 * AST) * 2)   // 92160 B

template<int LAYER>
__global__ void __launch_bounds__(256) k_gemm_tc(
        const float* __restrict__ bf_,
        const float* __restrict__ bb_) {
    constexpr int KPAD = LAYER ? KP1 : KP0;
    extern __shared__ __align__(16) char smc[];
    bf16* As[2];   // [hi/lo][64][AST]
    bf16* Bs[2];   // [hi/lo][256][AST]
    As[0] = (bf16*)smc;
    As[1] = As[0] + 64 * AST;
    Bs[0] = As[1] + 64 * AST;
    Bs[1] = Bs[0] + 256 * AST;

    const int dir = blockIdx.z;
    const int m0  = blockIdx.x * 64;
    const int n0  = blockIdx.y * 256;
    const bf16* __restrict__ asrc[2] = {
        LAYER ? g_a1h : g_a0h,
        LAYER ? g_a1l : g_a0l };
    const bf16* __restrict__ wsrc[2] = {
        (LAYER ? g_w1h : g_w0h) + (size_t)dir * GG * KPAD,
        (LAYER ? g_w1l : g_w0l) + (size_t)dir * GG * KPAD };
    const float* __restrict__ bias = dir ? bb_ : bf_;
    float* __restrict__ out = g_xz[dir];

    const int tid  = threadIdx.x;
    const int wid  = tid >> 5;
    const int lane = tid & 31;
    const int q = lane & 3;        // quad index
    const int g = lane >> 2;       // group (row/col within tile)
    const int mw = (wid & 1) * 32; // warp M offset
    const int nw = (wid >> 1) * 64;// warp N offset

    float acc[2][8][4];
    #pragma unroll
    for (int mt = 0; mt < 2; mt++)
        #pragma unroll
        for (int nt = 0; nt < 8; nt++)
            #pragma unroll
            for (int e = 0; e < 4; e++) acc[mt][nt][e] = 0.f;

    for (int k0 = 0; k0 < KPAD; k0 += 64) {
        if (k0) __syncthreads();
        // stage A hi/lo: 64 rows x 64 k
        #pragma unroll
        for (int h = 0; h < 2; h++) {
            #pragma unroll
            for (int p = 0; p < 2; p++) {
                int i = tid + 256 * p;
                int row = i >> 3, v = i & 7;
                *(uint4*)&As[h][row * AST + v * 8] =
                    *(const uint4*)(asrc[h] + (size_t)(m0 + row) * KPAD + k0 + v * 8);
            }
        }
        // stage B hi/lo: 256 n-rows x 64 k
        #pragma unroll
        for (int h = 0; h < 2; h++) {
            #pragma unroll
            for (int p = 0; p < 8; p++) {
                int i = tid + 256 * p;
                int row = i >> 3, v = i & 7;
                *(uint4*)&Bs[h][row * AST + v * 8] =
                    *(const uint4*)(wsrc[h] + (size_t)(n0 + row) * KPAD + k0 + v * 8);
            }
        }
        __syncthreads();

        #pragma unroll
        for (int ks = 0; ks < 4; ks++) {
            const int kb = ks * 16;
            unsigned afr[2][2][4];
            #pragma unroll
            for (int h = 0; h < 2; h++)
                #pragma unroll
                for (int mt = 0; mt < 2; mt++) {
                    int r = mw + mt * 16 + g;
                    afr[h][mt][0] = *(const unsigned*)&As[h][r * AST + kb + 2 * q];
                    afr[h][mt][1] = *(const unsigned*)&As[h][(r + 8) * AST + kb + 2 * q];
                    afr[h][mt][2] = *(const unsigned*)&As[h][r * AST + kb + 2 * q + 8];
                    afr[h][mt][3] = *(const unsigned*)&As[h][(r + 8) * AST + kb + 2 * q + 8];
                }
            unsigned bfr[2][8][2];
            #pragma unroll
            for (int h = 0; h < 2; h++)
                #pragma unroll
                for (int nt = 0; nt < 8; nt++) {
                    int n = nw + nt * 8 + g;
                    bfr[h][nt][0] = *(const unsigned*)&Bs[h][n * AST + kb + 2 * q];
                    bfr[h][nt][1] = *(const unsigned*)&Bs[h][n * AST + kb + 2 * q + 8];
                }
            #pragma unroll
            for (int mt = 0; mt < 2; mt++)
                #pragma unroll
                for (int nt = 0; nt < 8; nt++) {
                    mma_bf16(acc[mt][nt], afr[0][mt], bfr[0][nt]);
                    mma_bf16(acc[mt][nt], afr[0][mt], bfr[1][nt]);
                    mma_bf16(acc[mt][nt], afr[1][mt], bfr[0][nt]);
                }
        }
    }

    // epilogue: D rows g / g+8, cols 2q, 2q+1 per n-tile
    #pragma unroll
    for (int mt = 0; mt < 2; mt++) {
        int r = m0 + mw + mt * 16 + g;
        #pragma unroll
        for (int nt = 0; nt < 8; nt++) {
            int c = n0 + nw + nt * 8 + 2 * q;
            float b0 = __ldg(&bias[c]), b1 = __ldg(&bias[c + 1]);
            *(float2*)&out[(size_t)r * GG + c] =
                make_float2(acc[mt][nt][0] + b0, acc[mt][nt][1] + b1);
            *(float2*)&out[(size_t)(r + 8) * GG + c] =
                make_float2(acc[mt][nt][2] + b0, acc[mt][nt][3] + b1);
        }
    }
}

// ---------------- persistent LSTM recurrence (R7-verbatim) ------------------
template<bool STORE_HS>
__global__ void __launch_bounds__(128, 1) k_lstm_persist(
        const int* __restrict__ text,
        const float* __restrict__ Uf,
        const float* __restrict__ Ub) {
    extern __shared__ float sm[];
    ull*   Usd = (ull*)sm;            // [512][32] dup pairs (128KB)
    float* hsm = sm + 512 * 64;       // [64 k][64 b] tile (16KB)

    const int dir = blockIdx.y;
    const int h0  = blockIdx.x * 8;
    const float* __restrict__ U  = dir ? Ub : Uf;
    const float* __restrict__ xz = g_xz[dir];
    const int tid = threadIdx.x;
    const int tx  = tid & 7;
    const int ty  = tid >> 3;
    const int b0  = ty * 4;
    const int hid = h0 + tx;

    for (int i = tid; i < 512 * 32; i += 128) {
        int k = i >> 5, c = i & 31, g = c >> 3, hh = c & 7;
        float u = U[(size_t)k * GG + g * HH + h0 + hh];
        ull pr;
        asm("mov.b64 %0, {%1,%2};" : "=l"(pr) : "f"(u), "f"(u));
        Usd[i] = pr;
    }

    __stcg((float4*)&g_hT[dir][0][hid * BB + b0], make_float4(0.f, 0.f, 0.f, 0.f));
    float creg[4] = {0.f, 0.f, 0.f, 0.f};
    float hreg[4] = {0.f, 0.f, 0.f, 0.f};

    unsigned epoch = 0;
    __syncthreads();
    if (tid == 0) { __threadfence(); atomicAdd(&g_bar, 1u); }
    ++epoch;

    float xzr[4][4];
    int msk[4];
    {
        int t = dir ? (SS - 1) : 0;
        #pragma unroll
        for (int ib = 0; ib < 4; ib++) {
            size_t r = (size_t)(b0 + ib) * SS + t;
            msk[ib] = text[r];
            const float* xp = xz + r * GG + hid;
            xzr[ib][0] = xp[0];
            xzr[ib][1] = xp[HH];
            xzr[ib][2] = xp[2 * HH];
            xzr[ib][3] = xp[3 * HH];
        }
    }
    if (tid == 0) {
        unsigned tgt = epoch * NBLK;
        while (*(volatile unsigned*)&g_bar < tgt) __nanosleep(32);
        __threadfence();
    }
    __syncthreads();

    for (int p = 0; p < SS; p++) {
        const int t = dir ? (SS - 1 - p) : p;
        const float* __restrict__ hprev = g_hT[dir][p & 1];

        ull acc[2][4];
        #pragma unroll
        for (int qq = 0; qq < 2; qq++)
            #pragma unroll
            for (int g = 0; g < 4; g++) acc[qq][g] = 0ull;

        float4 pf[8];
        {
            const float4* src = (const float4*)hprev;
            #pragma unroll
            for (int i = 0; i < 8; i++) pf[i] = __ldcg(src + tid + 128 * i);
        }

        for (int k0 = 0; k0 < HH; k0 += 64) {
            __syncthreads();
            #pragma unroll
            for (int i = 0; i < 8; i++) ((float4*)hsm)[tid + 128 * i] = pf[i];
            if (k0 + 64 < HH) {
                const float4* nsrc = (const float4*)(hprev + (k0 + 64) * BB);
                #pragma unroll
                for (int i = 0; i < 8; i++) pf[i] = __ldcg(nsrc + tid + 128 * i);
            }
            __syncthreads();

            const ull* ub = Usd + (size_t)k0 * 32 + tx;
            #pragma unroll 16
            for (int kk = 0; kk < 64; kk++) {
                ulonglong2 hv = *(const ulonglong2*)&hsm[kk * 64 + b0];
                const ull* up = ub + (size_t)kk * 32;
                ull u0 = up[0], u1 = up[8], u2 = up[16], u3 = up[24];
                FMA2(acc[0][0], hv.x, u0, acc[0][0]);
                FMA2(acc[1][0], hv.y, u0, acc[1][0]);
                FMA2(acc[0][1], hv.x, u1, acc[0][1]);
                FMA2(acc[1][1], hv.y, u1, acc[1][1]);
                FMA2(acc[0][2], hv.x, u2, acc[0][2]);
                FMA2(acc[1][2], hv.y, u2, acc[1][2]);
                FMA2(acc[0][3], hv.x, u3, acc[0][3]);
                FMA2(acc[1][3], hv.y, u3, acc[1][3]);
            }
        }

        float zz[4][4];
        #pragma unroll
        for (int g = 0; g < 4; g++) {
            float lo, hi;
            asm("mov.b64 {%0,%1}, %2;" : "=f"(lo), "=f"(hi) : "l"(acc[0][g]));
            zz[0][g] = lo; zz[1][g] = hi;
            asm("mov.b64 {%0,%1}, %2;" : "=f"(lo), "=f"(hi) : "l"(acc[1][g]));
            zz[2][g] = lo; zz[3][g] = hi;
        }

        #pragma unroll
        for (int ib = 0; ib < 4; ib++) {
            float zi = zz[ib][0] + xzr[ib][0];
            float zf = zz[ib][1] + xzr[ib][1];
            float zg = zz[ib][2] + xzr[ib][2];
            float zo = zz[ib][3] + xzr[ib][3];
            float ig = 1.f / (1.f + __expf(-zi));
            float fg = 1.f / (1.f + __expf(-zf));
            float gg = tanhf(zg);
            float og = 1.f / (1.f + __expf(-zo));
            float cn = fg * creg[ib] + ig * gg;
            float hn = og * tanhf(cn);
            bool m = (msk[ib] != 0);
            creg[ib] = m ? cn : creg[ib];
            hreg[ib] = m ? hn : hreg[ib];
        }

        __stcg((float4*)&g_hT[dir][(p + 1) & 1][hid * BB + b0],
               make_float4(hreg[0], hreg[1], hreg[2], hreg[3]));

        __syncthreads();
        if (tid == 0) { __threadfence(); atomicAdd(&g_bar, 1u); }
        ++epoch;

        if (STORE_HS) {
            #pragma unroll
            for (int ib = 0; ib < 4; ib++)
                g_hs0[dir][((size_t)(b0 + ib) * SS + t) * HH + hid] = hreg[ib];
        }
        if (p + 1 < SS) {
            int t2 = dir ? (SS - 2 - p) : (p + 1);
            #pragma unroll
            for (int ib = 0; ib < 4; ib++) {
                size_t r = (size_t)(b0 + ib) * SS + t2;
                msk[ib] = text[r];
                const float* xp = xz + r * GG + hid;
                xzr[ib][0] = xp[0];
                xzr[ib][1] = xp[HH];
                xzr[ib][2] = xp[2 * HH];
                xzr[ib][3] = xp[3 * HH];
            }
        }
        if (tid == 0) {
            unsigned tgt = epoch * NBLK;
            while (*(volatile unsigned*)&g_bar < tgt) __nanosleep(32);
            __threadfence();
        }
        __syncthreads();
    }
}

// ---------------- dense head ------------------------------------------------
__global__ void k_dense0(const float* __restrict__ w, const float* __restrict__ bia) {
    int gw = (blockIdx.x * blockDim.x + threadIdx.x) >> 5;
    int lane = threadIdx.x & 31;
    if (gw >= BB * 512) return;
    int b = gw >> 9, j = gw & 511;
    float s = 0.f;
    for (int k = lane; k < KC; k += 32) {
        float a = (k < HH) ? g_hT[0][0][k * BB + b]
                           : g_hT[1][0][(k - HH) * BB + b];
        s += a * w[(size_t)k * 512 + j];
    }
    #pragma unroll
    for (int o = 16; o; o >>= 1) s += __shfl_xor_sync(0xffffffffu, s, o);
    if (!lane) {
        s += bia[j];
        g_fc1[b * 512 + j] = (s >= 0.f) ? s : 0.2f * s;
    }
}

__global__ void k_dense1(const float* __restrict__ w, const float* __restrict__ bia) {
    int gw = (blockIdx.x * blockDim.x + threadIdx.x) >> 5;
    int lane = threadIdx.x & 31;
    if (gw >= BB * 256) return;
    int b = gw >> 8, j = gw & 255;
    float s = 0.f;
    for (int k = lane; k < 512; k += 32)
        s += g_fc1[b * 512 + k] * w[(size_t)k * 256 + j];
    #pragma unroll
    for (int o = 16; o; o >>= 1) s += __shfl_xor_sync(0xffffffffu, s, o);
    if (!lane) {
        s += bia[j];
        g_fc2[b * 256 + j] = (s >= 0.f) ? s : 0.2f * s;
    }
}

__global__ void k_dense2(const float* __restrict__ w, const float* __restrict__ bia,
                         float* __restrict__ out) {
    int b = blockIdx.x;
    int lane = threadIdx.x;
    float s = 0.f;
    for (int k = lane; k < 256; k += 32)
        s += g_fc2[b * 256 + k] * w[k];
    #pragma unroll
    for (int o = 16; o; o >>= 1) s += __shfl_xor_sync(0xffffffffu, s, o);
    if (!lane) out[b] = s + bia[0];
}

// ---------------- launch ----------------------------------------------------
extern "C" void kernel_launch(void* const* d_in, const int* in_sizes, int n_in,
                              void* d_out, int out_size) {
    const int*   text = (const int*)  d_in[0];
    const float* emb  = (const float*)d_in[1];
    const float* W0f  = (const float*)d_in[2];
    const float* U0f  = (const float*)d_in[3];
    const float* b0f  = (const float*)d_in[4];
    const float* W0b  = (const float*)d_in[5];
    const float* U0b  = (const float*)d_in[6];
    const float* b0b  = (const float*)d_in[7];
    const float* W1f  = (const float*)d_in[8];
    const float* U1f  = (const float*)d_in[9];
    const float* b1f  = (const float*)d_in[10];
    const float* W1b  = (const float*)d_in[11];
    const float* U1b  = (const float*)d_in[12];
    const float* b1b  = (const float*)d_in[13];
    const float* d0w  = (const float*)d_in[14];
    const float* d0b  = (const float*)d_in[15];
    const float* d1w  = (const float*)d_in[16];
    const float* d1b  = (const float*)d_in[17];
    const float* d2w  = (const float*)d_in[18];
    const float* d2b  = (const float*)d_in[19];
    float* out = (float*)d_out;

    const int smemsz = (512 * 64 + 64 * 64) * 4;  // 147456 B (proven-safe)
    cudaFuncSetAttribute(k_lstm_persist<true>,
                         cudaFuncAttributeMaxDynamicSharedMemorySize, smemsz);
    cudaFuncSetAttribute(k_lstm_persist<false>,
                         cudaFuncAttributeMaxDynamicSharedMemorySize, smemsz);
    cudaFuncSetAttribute(k_gemm_tc<0>,
                         cudaFuncAttributeMaxDynamicSharedMemorySize, GEMM_SMEM);
    cudaFuncSetAttribute(k_gemm_tc<1>,
                         cudaFuncAttributeMaxDynamicSharedMemorySize, GEMM_SMEM);

    // ---- layer 0 ----  (GEMM at ncu's launch slot 3)
    k_zero_bar<<<1, 1>>>();                                        // 0
    k_split_a0<<<(BB * SS * KP0) / 256, 256>>>(text, emb);         // 1
    k_split_w<0><<<(2 * GG * KP0) / 256, 256>>>(W0f, W0b);         // 2
    k_gemm_tc<0><<<dim3(256, 8, 2), 256, GEMM_SMEM>>>(b0f, b0b);   // 3
    k_lstm_persist<true><<<dim3(64, 2), 128, smemsz>>>(text, U0f, U0b);

    // ---- layer 1 ----
    k_split_a1<<<(BB * SS * KP1) / 256, 256>>>();
    k_split_w<1><<<(2 * GG * KP1) / 256, 256>>>(W1f, W1b);
    k_zero_bar<<<1, 1>>>();
    k_gemm_tc<1><<<dim3(256, 8, 2), 256, GEMM_SMEM>>>(b1f, b1b);
    k_lstm_persist<false><<<dim3(64, 2), 128, smemsz>>>(text, U1f, U1b);

    // ---- dense head ----
    k_dense0<<<(BB * 512 * 32) / 256, 256>>>(d0w, d0b);
    k_dense1<<<(BB * 256 * 32) / 256, 256>>>(d1w, d1b);
    k_dense2<<<BB, 32>>>(d2w, d2b, out);
}

// round 16
// speedup vs baseline: 4.6696x; 1.4991x over previous
#include <cuda_runtime.h>
#include <cuda_bf16.h>
#include <cstdint>
#include <cstddef>

#define BB 64
#define SS 256
#define DD 300
#define HH 512
#define GG 2048   // 4*H
#define KC 1024   // 2*H
#define NBLK 128u
#define KP0 320   // layer0 K padded (300 -> 320)
#define KP1 1024  // layer1 K

typedef unsigned long long ull;
typedef __nv_bfloat16 bf16;

// ---------------- scratch (static device globals; no allocation) ------------
__device__ float g_xz[2][(size_t)BB * SS * GG];   // per-dir input projections
__device__ float g_hs0[2][(size_t)BB * SS * HH];  // layer-0 seq outputs (original t)
__device__ float g_hT[2][2][HH * BB];             // [dir][parity][h*BB + b]
__device__ float g_fc1[BB * 512];
__device__ float g_fc2[BB * 256];
__device__ unsigned g_bar;
// bf16 split buffers (GEMM inputs)
__device__ bf16 g_a0h[(size_t)BB * SS * KP0];
__device__ bf16 g_a0l[(size_t)BB * SS * KP0];
__device__ bf16 g_a1h[(size_t)BB * SS * KP1];
__device__ bf16 g_a1l[(size_t)BB * SS * KP1];
__device__ bf16 g_w0h[(size_t)2 * GG * KP0];  // [dir][j][k] transposed
__device__ bf16 g_w0l[(size_t)2 * GG * KP0];
__device__ bf16 g_w1h[(size_t)2 * GG * KP1];
__device__ bf16 g_w1l[(size_t)2 * GG * KP1];
// recurrence h state, bf16 hi/lo, [dir][parity][hl][b*HH + h]
__device__ bf16 g_hbf[2][2][2][(size_t)BB * HH];

// m16n8k16 bf16 mma (sm_80+ feature; compiles for plain sm_103 target)
__device__ __forceinline__ void mma_bf16(float* d, const unsigned* a, const unsigned* b) {
    asm("mma.sync.aligned.m16n8k16.row.col.f32.bf16.bf16.f32 "
        "{%0,%1,%2,%3}, {%4,%5,%6,%7}, {%8,%9}, {%0,%1,%2,%3};"
        : "+f"(d[0]), "+f"(d[1]), "+f"(d[2]), "+f"(d[3])
        : "r"(a[0]), "r"(a[1]), "r"(a[2]), "r"(a[3]), "r"(b[0]), "r"(b[1]));
}

__device__ __forceinline__ unsigned pack_bf2(bf16 a, bf16 b) {
    return (unsigned)__bfloat16_as_ushort(a) |
           ((unsigned)__bfloat16_as_ushort(b) << 16);
}

// ---------------- split kernels (fp32 -> bf16 hi/lo) -------------------------
__global__ void k_split_a0(const int* __restrict__ text,
                           const float* __restrict__ emb) {
    size_t i = (size_t)blockIdx.x * 256 + threadIdx.x;
    if (i >= (size_t)BB * SS * KP0) return;
    int k = (int)(i % KP0);
    size_t r = i / KP0;
    float v = (k < DD) ? emb[(size_t)text[r] * DD + k] : 0.f;
    bf16 h = __float2bfloat16(v);
    g_a0h[i] = h;
    g_a0l[i] = __float2bfloat16(v - __bfloat162float(h));
}

__global__ void k_split_a1() {
    size_t i = (size_t)blockIdx.x * 256 + threadIdx.x;
    if (i >= (size_t)BB * SS * KP1) return;
    int k = (int)(i & (KP1 - 1));
    size_t r = i >> 10;
    float v = (k < HH) ? g_hs0[0][r * HH + k] : g_hs0[1][r * HH + (k - HH)];
    bf16 h = __float2bfloat16(v);
    g_a1h[i] = h;
    g_a1l[i] = __float2bfloat16(v - __bfloat162float(h));
}

// W [K][2048] (per dir) -> transposed bf16 hi/lo [dir][2048][Kpad].
// Also resets the recurrence grid barrier (runs before each lstm launch).
template<int LAYER>
__global__ void k_split_w(const float* __restrict__ Wf,
                          const float* __restrict__ Wb) {
    constexpr int K    = LAYER ? KC : DD;
    constexpr int Kpad = LAYER ? KP1 : KP0;
    bf16* __restrict__ hiT = LAYER ? g_w1h : g_w0h;
    bf16* __restrict__ loT = LAYER ? g_w1l : g_w0l;
    if (blockIdx.x == 0 && threadIdx.x == 0) g_bar = 0u;
    size_t i = (size_t)blockIdx.x * 256 + threadIdx.x;
    if (i >= (size_t)2 * GG * Kpad) return;
    int k = (int)(i % Kpad);
    size_t jd = i / Kpad;
    int j = (int)(jd % GG);
    int d = (int)(jd / GG);
    float v = (k < K) ? (d ? Wb : Wf)[(size_t)k * GG + j] : 0.f;
    bf16 h = __float2bfloat16(v);
    hiT[i] = h;
    loT[i] = __float2bfloat16(v - __bfloat162float(h));
}

// ---------------- mma.sync bf16 split GEMM (verified in R14) -----------------
#define AST 72
#define GEMM_SMEM ((2 * 64 * AST + 2 * 256 * AST) * 2)   // 92160 B

template<int LAYER>
__global__ void __launch_bounds__(256) k_gemm_tc(
        const float* __restrict__ bf_,
        const float* __restrict__ bb_) {
    constexpr int KPAD = LAYER ? KP1 : KP0;
    extern __shared__ __align__(16) char smc[];
    bf16* As[2];
    bf16* Bs[2];
    As[0] = (bf16*)smc;
    As[1] = As[0] + 64 * AST;
    Bs[0] = As[1] + 64 * AST;
    Bs[1] = Bs[0] + 256 * AST;

    const int dir = blockIdx.z;
    const int m0  = blockIdx.x * 64;
    const int n0  = blockIdx.y * 256;
    const bf16* __restrict__ asrc[2] = {
        LAYER ? g_a1h : g_a0h,
        LAYER ? g_a1l : g_a0l };
    const bf16* __restrict__ wsrc[2] = {
        (LAYER ? g_w1h : g_w0h) + (size_t)dir * GG * KPAD,
        (LAYER ? g_w1l : g_w0l) + (size_t)dir * GG * KPAD };
    const float* __restrict__ bias = dir ? bb_ : bf_;
    float* __restrict__ out = g_xz[dir];

    const int tid  = threadIdx.x;
    const int wid  = tid >> 5;
    const int lane = tid & 31;
    const int q = lane & 3;
    const int g = lane >> 2;
    const int mw = (wid & 1) * 32;
    const int nw = (wid >> 1) * 64;

    float acc[2][8][4];
    #pragma unroll
    for (int mt = 0; mt < 2; mt++)
        #pragma unroll
        for (int nt = 0; nt < 8; nt++)
            #pragma unroll
            for (int e = 0; e < 4; e++) acc[mt][nt][e] = 0.f;

    for (int k0 = 0; k0 < KPAD; k0 += 64) {
        if (k0) __syncthreads();
        #pragma unroll
        for (int h = 0; h < 2; h++) {
            #pragma unroll
            for (int p = 0; p < 2; p++) {
                int i = tid + 256 * p;
                int row = i >> 3, v = i & 7;
                *(uint4*)&As[h][row * AST + v * 8] =
                    *(const uint4*)(asrc[h] + (size_t)(m0 + row) * KPAD + k0 + v * 8);
            }
        }
        #pragma unroll
        for (int h = 0; h < 2; h++) {
            #pragma unroll
            for (int p = 0; p < 8; p++) {
                int i = tid + 256 * p;
                int row = i >> 3, v = i & 7;
                *(uint4*)&Bs[h][row * AST + v * 8] =
                    *(const uint4*)(wsrc[h] + (size_t)(n0 + row) * KPAD + k0 + v * 8);
            }
        }
        __syncthreads();

        #pragma unroll
        for (int ks = 0; ks < 4; ks++) {
            const int kb = ks * 16;
            unsigned afr[2][2][4];
            #pragma unroll
            for (int h = 0; h < 2; h++)
                #pragma unroll
                for (int mt = 0; mt < 2; mt++) {
                    int r = mw + mt * 16 + g;
                    afr[h][mt][0] = *(const unsigned*)&As[h][r * AST + kb + 2 * q];
                    afr[h][mt][1] = *(const unsigned*)&As[h][(r + 8) * AST + kb + 2 * q];
                    afr[h][mt][2] = *(const unsigned*)&As[h][r * AST + kb + 2 * q + 8];
                    afr[h][mt][3] = *(const unsigned*)&As[h][(r + 8) * AST + kb + 2 * q + 8];
                }
            unsigned bfr[2][8][2];
            #pragma unroll
            for (int h = 0; h < 2; h++)
                #pragma unroll
                for (int nt = 0; nt < 8; nt++) {
                    int n = nw + nt * 8 + g;
                    bfr[h][nt][0] = *(const unsigned*)&Bs[h][n * AST + kb + 2 * q];
                    bfr[h][nt][1] = *(const unsigned*)&Bs[h][n * AST + kb + 2 * q + 8];
                }
            #pragma unroll
            for (int mt = 0; mt < 2; mt++)
                #pragma unroll
                for (int nt = 0; nt < 8; nt++) {
                    mma_bf16(acc[mt][nt], afr[0][mt], bfr[0][nt]);
                    mma_bf16(acc[mt][nt], afr[0][mt], bfr[1][nt]);
                    mma_bf16(acc[mt][nt], afr[1][mt], bfr[0][nt]);
                }
        }
    }

    #pragma unroll
    for (int mt = 0; mt < 2; mt++) {
        int r = m0 + mw + mt * 16 + g;
        #pragma unroll
        for (int nt = 0; nt < 8; nt++) {
            int c = n0 + nw + nt * 8 + 2 * q;
            float b0 = __ldg(&bias[c]), b1 = __ldg(&bias[c + 1]);
            *(float2*)&out[(size_t)r * GG + c] =
                make_float2(acc[mt][nt][0] + b0, acc[mt][nt][1] + b1);
            *(float2*)&out[(size_t)(r + 8) * GG + c] =
                make_float2(acc[mt][nt][2] + b0, acc[mt][nt][3] + b1);
        }
    }
}

// ---------------- persistent tensor-core LSTM recurrence ---------------------
// grid (64, 2 dirs), block 128 (4 warps), 1 block/SM via 147456 B dyn smem.
// Block owns 8 h-indices; z cols = nt*8+g  <->  gate=nt, hoff=g.
// U prepacked once into fragment-ordered smem; h exchanged as bf16 hi/lo via
// global double-buffer + R7 barrier. Split mma: AhBh + AhBl + AlBh.
static constexpr int OFF_AS = 65536;           // Upk: 2*4*32*32 ull = 64KB
static constexpr int OFF_ZS = 65536 + 34816;   // As: 2*64*136 bf16 = 34816B
#define LSTM_SMEM 147456                        // proven-safe size

template<bool STORE_HS>
__global__ void __launch_bounds__(128, 1) k_lstm_mma(
        const int* __restrict__ text,
        const float* __restrict__ Uf,
        const float* __restrict__ Ub) {
    extern __shared__ char smraw[];
    ull*   Upk = (ull*)smraw;                  // [hl][nt][ks][lane]
    bf16*  As  = (bf16*)(smraw + OFF_AS);      // [hl][64][136]
    float* zsm = (float*)(smraw + OFF_ZS);     // [64][36]

    const int dir = blockIdx.y;
    const int h0  = blockIdx.x * 8;
    const float* __restrict__ U  = dir ? Ub : Uf;
    const float* __restrict__ xz = g_xz[dir];
    const int tid  = threadIdx.x;
    const int lane = tid & 31;
    const int q = lane & 3;
    const int g = lane >> 2;
    const int rbase = (tid >> 5) * 16;
    const int bb    = tid & 63;     // epilogue batch
    const int hbase = tid >> 6;     // epilogue hoff = hbase + 2j

    // ---- prepack U fragments (once) ----
    // col n = nt*8+g  ->  U column nt*HH + h0 + g ; k = ks*16 + 2q
    #pragma unroll
    for (int nt = 0; nt < 4; nt++) {
        const float* ucol = U + (size_t)nt * HH + h0 + g;
        for (int ks = 0; ks < 32; ks++) {
            int k = ks * 16 + 2 * q;
            float v0 = ucol[(size_t)k * GG];
            float v1 = ucol[(size_t)(k + 1) * GG];
            float v2 = ucol[(size_t)(k + 8) * GG];
            float v3 = ucol[(size_t)(k + 9) * GG];
            bf16 h0b = __float2bfloat16(v0), h1b = __float2bfloat16(v1);
            bf16 h2b = __float2bfloat16(v2), h3b = __float2bfloat16(v3);
            bf16 l0b = __float2bfloat16(v0 - __bfloat162float(h0b));
            bf16 l1b = __float2bfloat16(v1 - __bfloat162float(h1b));
            bf16 l2b = __float2bfloat16(v2 - __bfloat162float(h2b));
            bf16 l3b = __float2bfloat16(v3 - __bfloat162float(h3b));
            ull hv = (ull)pack_bf2(h0b, h1b) | ((ull)pack_bf2(h2b, h3b) << 32);
            ull lv = (ull)pack_bf2(l0b, l1b) | ((ull)pack_bf2(l2b, l3b) << 32);
            Upk[((0 * 4 + nt) * 32 + ks) * 32 + lane] = hv;
            Upk[((1 * 4 + nt) * 32 + ks) * 32 + lane] = lv;
        }
    }

    // zero parity-0 h (owned cells) and register state
    bf16 z16 = __float2bfloat16(0.f);
    #pragma unroll
    for (int j = 0; j < 4; j++) {
        int hid = h0 + hbase + 2 * j;
        g_hbf[dir][0][0][(size_t)bb * HH + hid] = z16;
        g_hbf[dir][0][1][(size_t)bb * HH + hid] = z16;
    }
    float creg[4] = {0.f, 0.f, 0.f, 0.f};
    float hreg[4] = {0.f, 0.f, 0.f, 0.f};

    unsigned epoch = 0;
    __syncthreads();
    if (tid == 0) { __threadfence(); atomicAdd(&g_bar, 1u); }
    ++epoch;

    // step-0 prefetch (barrier shadow)
    float xzr[4][4];
    int msk;
    {
        int t = dir ? (SS - 1) : 0;
        msk = text[(size_t)bb * SS + t];
        const float* xp = xz + ((size_t)bb * SS + t) * GG + h0;
        #pragma unroll
        for (int j = 0; j < 4; j++)
            #pragma unroll
            for (int gt = 0; gt < 4; gt++)
                xzr[j][gt] = xp[gt * HH + hbase + 2 * j];
    }
    if (tid == 0) {
        unsigned tgt = epoch * NBLK;
        while (*(volatile unsigned*)&g_bar < tgt) __nanosleep(32);
        __threadfence();
    }
    __syncthreads();

    for (int p = 0; p < SS; p++) {
        const int t  = dir ? (SS - 1 - p) : p;
        const int par = p & 1;

        float acc[4][4];
        #pragma unroll
        for (int nt = 0; nt < 4; nt++)
            #pragma unroll
            for (int e = 0; e < 4; e++) acc[nt][e] = 0.f;

        for (int ck = 0; ck < 4; ck++) {
            const int k0 = ck * 128;
            if (ck) __syncthreads();
            // stage A chunk: [hl][64 rows][128 k] bf16 from global h
            #pragma unroll
            for (int hl = 0; hl < 2; hl++) {
                const bf16* src = g_hbf[dir][par][hl];
                #pragma unroll
                for (int j = 0; j < 8; j++) {
                    int idx = tid + 128 * j;
                    int row = idx >> 4, seg = idx & 15;
                    uint4 v = __ldcg((const uint4*)(src + (size_t)row * HH + k0 + seg * 8));
                    *(uint4*)&As[hl * 8704 + row * 136 + seg * 8] = v;
                }
            }
            __syncthreads();

            #pragma unroll
            for (int ks8 = 0; ks8 < 8; ks8++) {
                const int kb = ks8 * 16;
                const int ks = ck * 8 + ks8;
                unsigned afr[2][4];
                #pragma unroll
                for (int hl = 0; hl < 2; hl++) {
                    const bf16* ab = As + hl * 8704;
                    int r = rbase + g;
                    afr[hl][0] = *(const unsigned*)&ab[r * 136 + kb + 2 * q];
                    afr[hl][1] = *(const unsigned*)&ab[(r + 8) * 136 + kb + 2 * q];
                    afr[hl][2] = *(const unsigned*)&ab[r * 136 + kb + 2 * q + 8];
                    afr[hl][3] = *(const unsigned*)&ab[(r + 8) * 136 + kb + 2 * q + 8];
                }
                #pragma unroll
                for (int nt = 0; nt < 4; nt++) {
                    ull bh = Upk[((0 * 4 + nt) * 32 + ks) * 32 + lane];
                    ull bl = Upk[((1 * 4 + nt) * 32 + ks) * 32 + lane];
                    mma_bf16(acc[nt], afr[0], (const unsigned*)&bh);
                    mma_bf16(acc[nt], afr[0], (const unsigned*)&bl);
                    mma_bf16(acc[nt], afr[1], (const unsigned*)&bh);
                }
            }
        }

        // z -> smem roundtrip (warps own disjoint row ranges)
        #pragma unroll
        for (int nt = 0; nt < 4; nt++) {
            int c = nt * 8 + 2 * q;
            zsm[(rbase + g) * 36 + c]     = acc[nt][0];
            zsm[(rbase + g) * 36 + c + 1] = acc[nt][1];
            zsm[(rbase + g + 8) * 36 + c]     = acc[nt][2];
            zsm[(rbase + g + 8) * 36 + c + 1] = acc[nt][3];
        }
        __syncthreads();

        // pointwise LSTM epilogue: 4 cells (bb, hbase+2j)
        const int np = par ^ 1;
        bool m = (msk != 0);
        #pragma unroll
        for (int j = 0; j < 4; j++) {
            int hoff = hbase + 2 * j;
            float zi = zsm[bb * 36 + 0 * 8 + hoff] + xzr[j][0];
            float zf = zsm[bb * 36 + 1 * 8 + hoff] + xzr[j][1];
            float zg = zsm[bb * 36 + 2 * 8 + hoff] + xzr[j][2];
            float zo = zsm[bb * 36 + 3 * 8 + hoff] + xzr[j][3];
            float ig = 1.f / (1.f + __expf(-zi));
            float fg = 1.f / (1.f + __expf(-zf));
            float gg = tanhf(zg);
            float og = 1.f / (1.f + __expf(-zo));
            float cn = fg * creg[j] + ig * gg;
            float hn = og * tanhf(cn);
            creg[j] = m ? cn : creg[j];
            hreg[j] = m ? hn : hreg[j];
            int hid = h0 + hoff;
            bf16 hh = __float2bfloat16(hreg[j]);
            bf16 hl_ = __float2bfloat16(hreg[j] - __bfloat162float(hh));
            g_hbf[dir][np][0][(size_t)bb * HH + hid] = hh;
            g_hbf[dir][np][1][(size_t)bb * HH + hid] = hl_;
            if (p == SS - 1) g_hT[dir][0][hid * BB + bb] = hreg[j];
        }

        __syncthreads();
        if (tid == 0) { __threadfence(); atomicAdd(&g_bar, 1u); }
        ++epoch;

        // barrier shadow: hs0 scatter + next-step prefetch
        if (STORE_HS) {
            #pragma unroll
            for (int j = 0; j < 4; j++)
                g_hs0[dir][((size_t)bb * SS + t) * HH + h0 + hbase + 2 * j] = hreg[j];
        }
        if (p + 1 < SS) {
            int t2 = dir ? (SS - 2 - p) : (p + 1);
            msk = text[(size_t)bb * SS + t2];
            const float* xp = xz + ((size_t)bb * SS + t2) * GG + h0;
            #pragma unroll
            for (int j = 0; j < 4; j++)
                #pragma unroll
                for (int gt = 0; gt < 4; gt++)
                    xzr[j][gt] = xp[gt * HH + hbase + 2 * j];
        }
        if (tid == 0) {
            unsigned tgt = epoch * NBLK;
            while (*(volatile unsigned*)&g_bar < tgt) __nanosleep(32);
            __threadfence();
        }
        __syncthreads();
    }
}

// ---------------- dense head ------------------------------------------------
__global__ void k_dense0(const float* __restrict__ w, const float* __restrict__ bia) {
    int gw = (blockIdx.x * blockDim.x + threadIdx.x) >> 5;
    int lane = threadIdx.x & 31;
    if (gw >= BB * 512) return;
    int b = gw >> 9, j = gw & 511;
    float s = 0.f;
    for (int k = lane; k < KC; k += 32) {
        float a = (k < HH) ? g_hT[0][0][k * BB + b]
                           : g_hT[1][0][(k - HH) * BB + b];
        s += a * w[(size_t)k * 512 + j];
    }
    #pragma unroll
    for (int o = 16; o; o >>= 1) s += __shfl_xor_sync(0xffffffffu, s, o);
    if (!lane) {
        s += bia[j];
        g_fc1[b * 512 + j] = (s >= 0.f) ? s : 0.2f * s;
    }
}

__global__ void k_dense1(const float* __restrict__ w, const float* __restrict__ bia) {
    int gw = (blockIdx.x * blockDim.x + threadIdx.x) >> 5;
    int lane = threadIdx.x & 31;
    if (gw >= BB * 256) return;
    int b = gw >> 8, j = gw & 255;
    float s = 0.f;
    for (int k = lane; k < 512; k += 32)
        s += g_fc1[b * 512 + k] * w[(size_t)k * 256 + j];
    #pragma unroll
    for (int o = 16; o; o >>= 1) s += __shfl_xor_sync(0xffffffffu, s, o);
    if (!lane) {
        s += bia[j];
        g_fc2[b * 256 + j] = (s >= 0.f) ? s : 0.2f * s;
    }
}

__global__ void k_dense2(const float* __restrict__ w, const float* __restrict__ bia,
                         float* __restrict__ out) {
    int b = blockIdx.x;
    int lane = threadIdx.x;
    float s = 0.f;
    for (int k = lane; k < 256; k += 32)
        s += g_fc2[b * 256 + k] * w[k];
    #pragma unroll
    for (int o = 16; o; o >>= 1) s += __shfl_xor_sync(0xffffffffu, s, o);
    if (!lane) out[b] = s + bia[0];
}

// ---------------- launch ----------------------------------------------------
extern "C" void kernel_launch(void* const* d_in, const int* in_sizes, int n_in,
                              void* d_out, int out_size) {
    const int*   text = (const int*)  d_in[0];
    const float* emb  = (const float*)d_in[1];
    const float* W0f  = (const float*)d_in[2];
    const float* U0f  = (const float*)d_in[3];
    const float* b0f  = (const float*)d_in[4];
    const float* W0b  = (const float*)d_in[5];
    const float* U0b  = (const float*)d_in[6];
    const float* b0b  = (const float*)d_in[7];
    const float* W1f  = (const float*)d_in[8];
    const float* U1f  = (const float*)d_in[9];
    const float* b1f  = (const float*)d_in[10];
    const float* W1b  = (const float*)d_in[11];
    const float* U1b  = (const float*)d_in[12];
    const float* b1b  = (const float*)d_in[13];
    const float* d0w  = (const float*)d_in[14];
    const float* d0b  = (const float*)d_in[15];
    const float* d1w  = (const float*)d_in[16];
    const float* d1b  = (const float*)d_in[17];
    const float* d2w  = (const float*)d_in[18];
    const float* d2b  = (const float*)d_in[19];
    float* out = (float*)d_out;

    cudaFuncSetAttribute(k_lstm_mma<true>,
                         cudaFuncAttributeMaxDynamicSharedMemorySize, LSTM_SMEM);
    cudaFuncSetAttribute(k_lstm_mma<false>,
                         cudaFuncAttributeMaxDynamicSharedMemorySize, LSTM_SMEM);
    cudaFuncSetAttribute(k_gemm_tc<0>,
                         cudaFuncAttributeMaxDynamicSharedMemorySize, GEMM_SMEM);
    cudaFuncSetAttribute(k_gemm_tc<1>,
                         cudaFuncAttributeMaxDynamicSharedMemorySize, GEMM_SMEM);

    // ---- layer 0 ----  (recurrence at ncu's launch slot 3)
    k_split_a0<<<(BB * SS * KP0) / 256, 256>>>(text, emb);              // 0
    k_split_w<0><<<(2 * GG * KP0) / 256, 256>>>(W0f, W0b);              // 1 (+bar reset)
    k_gemm_tc<0><<<dim3(256, 8, 2), 256, GEMM_SMEM>>>(b0f, b0b);        // 2
    k_lstm_mma<true><<<dim3(64, 2), 128, LSTM_SMEM>>>(text, U0f, U0b);  // 3

    // ---- layer 1 ----
    k_split_a1<<<(BB * SS * KP1) / 256, 256>>>();
    k_split_w<1><<<(2 * GG * KP1) / 256, 256>>>(W1f, W1b);              // (+bar reset)
    k_gemm_tc<1><<<dim3(256, 8, 2), 256, GEMM_SMEM>>>(b1f, b1b);
    k_lstm_mma<false><<<dim3(64, 2), 128, LSTM_SMEM>>>(text, U1f, U1b);

    // ---- dense head ----
    k_dense0<<<(BB * 512 * 32) / 256, 256>>>(d0w, d0b);
    k_dense1<<<(BB * 256 * 32) / 256, 256>>>(d1w, d1b);
    k_dense2<<<BB, 32>>>(d2w, d2b, out);
}

// round 17
// speedup vs baseline: 5.1511x; 1.1031x over previous
#include <cuda_runtime.h>
#include <cuda_bf16.h>
#include <cstdint>
#include <cstddef>

#define BB 64
#define SS 256
#define DD 300
#define HH 512
#define GG 2048   // 4*H
#define KC 1024   // 2*H
#define NBLK 128u
#define KP0 320   // layer0 K padded (300 -> 320)
#define KP1 1024  // layer1 K

typedef unsigned long long ull;
typedef __nv_bfloat16 bf16;

// ---------------- scratch (static device globals; no allocation) ------------
__device__ float g_xz[2][(size_t)BB * SS * GG];   // per-dir input projections
__device__ float g_hs0[2][(size_t)BB * SS * HH];  // layer-0 seq outputs (original t)
__device__ float g_hT[2][2][HH * BB];             // [dir][parity][h*BB + b]
__device__ float g_fc1[BB * 512];
__device__ float g_fc2[BB * 256];
__device__ unsigned g_bar;
// bf16 split buffers (GEMM inputs)
__device__ bf16 g_a0h[(size_t)BB * SS * KP0];
__device__ bf16 g_a0l[(size_t)BB * SS * KP0];
__device__ bf16 g_a1h[(size_t)BB * SS * KP1];
__device__ bf16 g_a1l[(size_t)BB * SS * KP1];
__device__ bf16 g_w0h[(size_t)2 * GG * KP0];  // [dir][j][k] transposed
__device__ bf16 g_w0l[(size_t)2 * GG * KP0];
__device__ bf16 g_w1h[(size_t)2 * GG * KP1];
__device__ bf16 g_w1l[(size_t)2 * GG * KP1];
// recurrence h state, bf16 hi/lo, [dir][parity][hl][b*HH + h]
__device__ bf16 g_hbf[2][2][2][(size_t)BB * HH];

// m16n8k16 bf16 mma (sm_80+ feature; compiles for plain sm_103 target)
__device__ __forceinline__ void mma_bf16(float* d, const unsigned* a, const unsigned* b) {
    asm("mma.sync.aligned.m16n8k16.row.col.f32.bf16.bf16.f32 "
        "{%0,%1,%2,%3}, {%4,%5,%6,%7}, {%8,%9}, {%0,%1,%2,%3};"
        : "+f"(d[0]), "+f"(d[1]), "+f"(d[2]), "+f"(d[3])
        : "r"(a[0]), "r"(a[1]), "r"(a[2]), "r"(a[3]), "r"(b[0]), "r"(b[1]));
}

__device__ __forceinline__ unsigned pack_bf2(bf16 a, bf16 b) {
    return (unsigned)__bfloat16_as_ushort(a) |
           ((unsigned)__bfloat16_as_ushort(b) << 16);
}

// ---------------- split kernels (fp32 -> bf16 hi/lo) -------------------------
__global__ void k_split_a0(const int* __restrict__ text,
                           const float* __restrict__ emb) {
    size_t i = (size_t)blockIdx.x * 256 + threadIdx.x;
    if (i >= (size_t)BB * SS * KP0) return;
    int k = (int)(i % KP0);
    size_t r = i / KP0;
    float v = (k < DD) ? emb[(size_t)text[r] * DD + k] : 0.f;
    bf16 h = __float2bfloat16(v);
    g_a0h[i] = h;
    g_a0l[i] = __float2bfloat16(v - __bfloat162float(h));
}

__global__ void k_split_a1() {
    size_t i = (size_t)blockIdx.x * 256 + threadIdx.x;
    if (i >= (size_t)BB * SS * KP1) return;
    int k = (int)(i & (KP1 - 1));
    size_t r = i >> 10;
    float v = (k < HH) ? g_hs0[0][r * HH + k] : g_hs0[1][r * HH + (k - HH)];
    bf16 h = __float2bfloat16(v);
    g_a1h[i] = h;
    g_a1l[i] = __float2bfloat16(v - __bfloat162float(h));
}

// W [K][2048] (per dir) -> transposed bf16 hi/lo [dir][2048][Kpad].
// Also resets the recurrence grid barrier (runs before each lstm launch).
template<int LAYER>
__global__ void k_split_w(const float* __restrict__ Wf,
                          const float* __restrict__ Wb) {
    constexpr int K    = LAYER ? KC : DD;
    constexpr int Kpad = LAYER ? KP1 : KP0;
    bf16* __restrict__ hiT = LAYER ? g_w1h : g_w0h;
    bf16* __restrict__ loT = LAYER ? g_w1l : g_w0l;
    if (blockIdx.x == 0 && threadIdx.x == 0) g_bar = 0u;
    size_t i = (size_t)blockIdx.x * 256 + threadIdx.x;
    if (i >= (size_t)2 * GG * Kpad) return;
    int k = (int)(i % Kpad);
    size_t jd = i / Kpad;
    int j = (int)(jd % GG);
    int d = (int)(jd / GG);
    float v = (k < K) ? (d ? Wb : Wf)[(size_t)k * GG + j] : 0.f;
    bf16 h = __float2bfloat16(v);
    hiT[i] = h;
    loT[i] = __float2bfloat16(v - __bfloat162float(h));
}

// ---------------- mma.sync bf16 split GEMM (R14-verified mapping) ------------
// Now with register double-buffering of the next K-chunk (R7 pattern).
#define AST 72
#define GEMM_SMEM ((2 * 64 * AST + 2 * 256 * AST) * 2)   // 92160 B

template<int LAYER>
__global__ void __launch_bounds__(256) k_gemm_tc(
        const float* __restrict__ bf_,
        const float* __restrict__ bb_) {
    constexpr int KPAD = LAYER ? KP1 : KP0;
    extern __shared__ __align__(16) char smc[];
    bf16* As[2];
    bf16* Bs[2];
    As[0] = (bf16*)smc;
    As[1] = As[0] + 64 * AST;
    Bs[0] = As[1] + 64 * AST;
    Bs[1] = Bs[0] + 256 * AST;

    const int dir = blockIdx.z;
    const int m0  = blockIdx.x * 64;
    const int n0  = blockIdx.y * 256;
    const bf16* __restrict__ asrc[2] = {
        LAYER ? g_a1h : g_a0h,
        LAYER ? g_a1l : g_a0l };
    const bf16* __restrict__ wsrc[2] = {
        (LAYER ? g_w1h : g_w0h) + (size_t)dir * GG * KPAD,
        (LAYER ? g_w1l : g_w0l) + (size_t)dir * GG * KPAD };
    const float* __restrict__ bias = dir ? bb_ : bf_;
    float* __restrict__ out = g_xz[dir];

    const int tid  = threadIdx.x;
    const int wid  = tid >> 5;
    const int lane = tid & 31;
    const int q = lane & 3;
    const int g = lane >> 2;
    const int mw = (wid & 1) * 32;
    const int nw = (wid >> 1) * 64;

    // per-thread staging coordinates
    const int arow = tid >> 3, aseg = tid & 7;           // A: rows 0..31 (+32)
    const int brow = tid >> 3, bseg = tid & 7;           // B: rows 0..31 (+32*p)

    float acc[2][8][4];
    #pragma unroll
    for (int mt = 0; mt < 2; mt++)
        #pragma unroll
        for (int nt = 0; nt < 8; nt++)
            #pragma unroll
            for (int e = 0; e < 4; e++) acc[mt][nt][e] = 0.f;

    uint4 pfA[2][2], pfB[2][8];
    // prefetch chunk 0
    #pragma unroll
    for (int h = 0; h < 2; h++) {
        #pragma unroll
        for (int p = 0; p < 2; p++)
            pfA[h][p] = *(const uint4*)(asrc[h] +
                (size_t)(m0 + arow + 32 * p) * KPAD + aseg * 8);
        #pragma unroll
        for (int p = 0; p < 8; p++)
            pfB[h][p] = *(const uint4*)(wsrc[h] +
                (size_t)(n0 + brow + 32 * p) * KPAD + bseg * 8);
    }

    for (int k0 = 0; k0 < KPAD; k0 += 64) {
        if (k0) __syncthreads();   // previous tile fully consumed
        #pragma unroll
        for (int h = 0; h < 2; h++) {
            #pragma unroll
            for (int p = 0; p < 2; p++)
                *(uint4*)&As[h][(arow + 32 * p) * AST + aseg * 8] = pfA[h][p];
            #pragma unroll
            for (int p = 0; p < 8; p++)
                *(uint4*)&Bs[h][(brow + 32 * p) * AST + bseg * 8] = pfB[h][p];
        }
        if (k0 + 64 < KPAD) {
            const int kn = k0 + 64;
            #pragma unroll
            for (int h = 0; h < 2; h++) {
                #pragma unroll
                for (int p = 0; p < 2; p++)
                    pfA[h][p] = *(const uint4*)(asrc[h] +
                        (size_t)(m0 + arow + 32 * p) * KPAD + kn + aseg * 8);
                #pragma unroll
                for (int p = 0; p < 8; p++)
                    pfB[h][p] = *(const uint4*)(wsrc[h] +
                        (size_t)(n0 + brow + 32 * p) * KPAD + kn + bseg * 8);
            }
        }
        __syncthreads();

        #pragma unroll
        for (int ks = 0; ks < 4; ks++) {
            const int kb = ks * 16;
            unsigned afr[2][2][4];
            #pragma unroll
            for (int h = 0; h < 2; h++)
                #pragma unroll
                for (int mt = 0; mt < 2; mt++) {
                    int r = mw + mt * 16 + g;
                    afr[h][mt][0] = *(const unsigned*)&As[h][r * AST + kb + 2 * q];
                    afr[h][mt][1] = *(const unsigned*)&As[h][(r + 8) * AST + kb + 2 * q];
                    afr[h][mt][2] = *(const unsigned*)&As[h][r * AST + kb + 2 * q + 8];
                    afr[h][mt][3] = *(const unsigned*)&As[h][(r + 8) * AST + kb + 2 * q + 8];
                }
            unsigned bfr[2][8][2];
            #pragma unroll
            for (int h = 0; h < 2; h++)
                #pragma unroll
                for (int nt = 0; nt < 8; nt++) {
                    int n = nw + nt * 8 + g;
                    bfr[h][nt][0] = *(const unsigned*)&Bs[h][n * AST + kb + 2 * q];
                    bfr[h][nt][1] = *(const unsigned*)&Bs[h][n * AST + kb + 2 * q + 8];
                }
            #pragma unroll
            for (int mt = 0; mt < 2; mt++)
                #pragma unroll
                for (int nt = 0; nt < 8; nt++) {
                    mma_bf16(acc[mt][nt], afr[0][mt], bfr[0][nt]);
                    mma_bf16(acc[mt][nt], afr[0][mt], bfr[1][nt]);
                    mma_bf16(acc[mt][nt], afr[1][mt], bfr[0][nt]);
                }
        }
    }

    #pragma unroll
    for (int mt = 0; mt < 2; mt++) {
        int r = m0 + mw + mt * 16 + g;
        #pragma unroll
        for (int nt = 0; nt < 8; nt++) {
            int c = n0 + nw + nt * 8 + 2 * q;
            float b0 = __ldg(&bias[c]), b1 = __ldg(&bias[c + 1]);
            *(float2*)&out[(size_t)r * GG + c] =
                make_float2(acc[mt][nt][0] + b0, acc[mt][nt][1] + b1);
            *(float2*)&out[(size_t)(r + 8) * GG + c] =
                make_float2(acc[mt][nt][2] + b0, acc[mt][nt][3] + b1);
        }
    }
}

// ---------------- persistent tensor-core LSTM recurrence ---------------------
// R16 structure + register prefetch of the next A chunk (R7 pattern).
static constexpr int OFF_AS = 65536;           // Upk: 2*4*32*32 ull = 64KB
static constexpr int OFF_ZS = 65536 + 34816;   // As: 2*64*136 bf16 = 34816B
#define LSTM_SMEM 147456                        // proven-safe size

template<bool STORE_HS>
__global__ void __launch_bounds__(128, 1) k_lstm_mma(
        const int* __restrict__ text,
        const float* __restrict__ Uf,
        const float* __restrict__ Ub) {
    extern __shared__ char smraw[];
    ull*   Upk = (ull*)smraw;                  // [hl][nt][ks][lane]
    bf16*  As  = (bf16*)(smraw + OFF_AS);      // [hl][64][136]
    float* zsm = (float*)(smraw + OFF_ZS);     // [64][36]

    const int dir = blockIdx.y;
    const int h0  = blockIdx.x * 8;
    const float* __restrict__ U  = dir ? Ub : Uf;
    const float* __restrict__ xz = g_xz[dir];
    const int tid  = threadIdx.x;
    const int lane = tid & 31;
    const int q = lane & 3;
    const int g = lane >> 2;
    const int rbase = (tid >> 5) * 16;
    const int bb    = tid & 63;     // epilogue batch
    const int hbase = tid >> 6;     // epilogue hoff = hbase + 2j
    const int srow = tid >> 4, sseg = tid & 15;   // A staging coords

    // ---- prepack U fragments (once) ----
    #pragma unroll
    for (int nt = 0; nt < 4; nt++) {
        const float* ucol = U + (size_t)nt * HH + h0 + g;
        for (int ks = 0; ks < 32; ks++) {
            int k = ks * 16 + 2 * q;
            float v0 = ucol[(size_t)k * GG];
            float v1 = ucol[(size_t)(k + 1) * GG];
            float v2 = ucol[(size_t)(k + 8) * GG];
            float v3 = ucol[(size_t)(k + 9) * GG];
            bf16 h0b = __float2bfloat16(v0), h1b = __float2bfloat16(v1);
            bf16 h2b = __float2bfloat16(v2), h3b = __float2bfloat16(v3);
            bf16 l0b = __float2bfloat16(v0 - __bfloat162float(h0b));
            bf16 l1b = __float2bfloat16(v1 - __bfloat162float(h1b));
            bf16 l2b = __float2bfloat16(v2 - __bfloat162float(h2b));
            bf16 l3b = __float2bfloat16(v3 - __bfloat162float(h3b));
            ull hv = (ull)pack_bf2(h0b, h1b) | ((ull)pack_bf2(h2b, h3b) << 32);
            ull lv = (ull)pack_bf2(l0b, l1b) | ((ull)pack_bf2(l2b, l3b) << 32);
            Upk[((0 * 4 + nt) * 32 + ks) * 32 + lane] = hv;
            Upk[((1 * 4 + nt) * 32 + ks) * 32 + lane] = lv;
        }
    }

    // zero parity-0 h (owned cells) and register state
    bf16 z16 = __float2bfloat16(0.f);
    #pragma unroll
    for (int j = 0; j < 4; j++) {
        int hid = h0 + hbase + 2 * j;
        g_hbf[dir][0][0][(size_t)bb * HH + hid] = z16;
        g_hbf[dir][0][1][(size_t)bb * HH + hid] = z16;
    }
    float creg[4] = {0.f, 0.f, 0.f, 0.f};
    float hreg[4] = {0.f, 0.f, 0.f, 0.f};

    unsigned epoch = 0;
    __syncthreads();
    if (tid == 0) { __threadfence(); atomicAdd(&g_bar, 1u); }
    ++epoch;

    // step-0 prefetch (barrier shadow)
    float xzr[4][4];
    int msk;
    {
        int t = dir ? (SS - 1) : 0;
        msk = text[(size_t)bb * SS + t];
        const float* xp = xz + ((size_t)bb * SS + t) * GG + h0;
        #pragma unroll
        for (int j = 0; j < 4; j++)
            #pragma unroll
            for (int gt = 0; gt < 4; gt++)
                xzr[j][gt] = xp[gt * HH + hbase + 2 * j];
    }
    if (tid == 0) {
        unsigned tgt = epoch * NBLK;
        while (*(volatile unsigned*)&g_bar < tgt) __nanosleep(32);
        __threadfence();
    }
    __syncthreads();

    for (int p = 0; p < SS; p++) {
        const int t  = dir ? (SS - 1 - p) : p;
        const int par = p & 1;

        float acc[4][4];
        #pragma unroll
        for (int nt = 0; nt < 4; nt++)
            #pragma unroll
            for (int e = 0; e < 4; e++) acc[nt][e] = 0.f;

        // prefetch chunk 0 into registers
        uint4 pf[2][4];
        #pragma unroll
        for (int hl = 0; hl < 2; hl++) {
            const bf16* src = g_hbf[dir][par][hl];
            #pragma unroll
            for (int j = 0; j < 4; j++) {
                int idx = tid + 128 * (2 * j + (tid >> 6 ? 0 : 0));  // plain 4x
                (void)idx;
                int ii = tid + 128 * j * 2;  // j covers 0,2,4,6 slots? no:
                (void)ii;
                pf[hl][j] = make_uint4(0, 0, 0, 0);
            }
        }
        // (clean version below — 8 uint4 per hl split as two halves of 4)
        uint4 pfa[2][8];
        #pragma unroll
        for (int hl = 0; hl < 2; hl++) {
            const bf16* src = g_hbf[dir][par][hl];
            #pragma unroll
            for (int j = 0; j < 8; j++) {
                int idx = tid + 128 * j;
                int row = idx >> 4, seg = idx & 15;
                pfa[hl][j] = __ldcg((const uint4*)(src + (size_t)row * HH + seg * 8));
            }
        }

        for (int ck = 0; ck < 4; ck++) {
            if (ck) __syncthreads();   // previous chunk consumed
            #pragma unroll
            for (int hl = 0; hl < 2; hl++) {
                #pragma unroll
                for (int j = 0; j < 8; j++) {
                    int idx = tid + 128 * j;
                    int row = idx >> 4, seg = idx & 15;
                    *(uint4*)&As[hl * 8704 + row * 136 + seg * 8] = pfa[hl][j];
                }
            }
            if (ck < 3) {
                const int kn = (ck + 1) * 128;
                #pragma unroll
                for (int hl = 0; hl < 2; hl++) {
                    const bf16* src = g_hbf[dir][par][hl];
                    #pragma unroll
                    for (int j = 0; j < 8; j++) {
                        int idx = tid + 128 * j;
                        int row = idx >> 4, seg = idx & 15;
                        pfa[hl][j] = __ldcg((const uint4*)(src + (size_t)row * HH + kn + seg * 8));
                    }
                }
            }
            __syncthreads();

            #pragma unroll
            for (int ks8 = 0; ks8 < 8; ks8++) {
                const int kb = ks8 * 16;
                const int ks = ck * 8 + ks8;
                unsigned afr[2][4];
                #pragma unroll
                for (int hl = 0; hl < 2; hl++) {
                    const bf16* ab = As + hl * 8704;
                    int r = rbase + g;
                    afr[hl][0] = *(const unsigned*)&ab[r * 136 + kb + 2 * q];
                    afr[hl][1] = *(const unsigned*)&ab[(r + 8) * 136 + kb + 2 * q];
                    afr[hl][2] = *(const unsigned*)&ab[r * 136 + kb + 2 * q + 8];
                    afr[hl][3] = *(const unsigned*)&ab[(r + 8) * 136 + kb + 2 * q + 8];
                }
                #pragma unroll
                for (int nt = 0; nt < 4; nt++) {
                    ull bh = Upk[((0 * 4 + nt) * 32 + ks) * 32 + lane];
                    ull bl = Upk[((1 * 4 + nt) * 32 + ks) * 32 + lane];
                    mma_bf16(acc[nt], afr[0], (const unsigned*)&bh);
                    mma_bf16(acc[nt], afr[0], (const unsigned*)&bl);
                    mma_bf16(acc[nt], afr[1], (const unsigned*)&bh);
                }
            }
        }

        // z -> smem roundtrip
        #pragma unroll
        for (int nt = 0; nt < 4; nt++) {
            int c = nt * 8 + 2 * q;
            zsm[(rbase + g) * 36 + c]     = acc[nt][0];
            zsm[(rbase + g) * 36 + c + 1] = acc[nt][1];
            zsm[(rbase + g + 8) * 36 + c]     = acc[nt][2];
            zsm[(rbase + g + 8) * 36 + c + 1] = acc[nt][3];
        }
        __syncthreads();

        // pointwise LSTM epilogue
        const int np = par ^ 1;
        bool m = (msk != 0);
        #pragma unroll
        for (int j = 0; j < 4; j++) {
            int hoff = hbase + 2 * j;
            float zi = zsm[bb * 36 + 0 * 8 + hoff] + xzr[j][0];
            float zf = zsm[bb * 36 + 1 * 8 + hoff] + xzr[j][1];
            float zg = zsm[bb * 36 + 2 * 8 + hoff] + xzr[j][2];
            float zo = zsm[bb * 36 + 3 * 8 + hoff] + xzr[j][3];
            float ig = 1.f / (1.f + __expf(-zi));
            float fg = 1.f / (1.f + __expf(-zf));
            float gg = tanhf(zg);
            float og = 1.f / (1.f + __expf(-zo));
            float cn = fg * creg[j] + ig * gg;
            float hn = og * tanhf(cn);
            creg[j] = m ? cn : creg[j];
            hreg[j] = m ? hn : hreg[j];
            int hid = h0 + hoff;
            bf16 hh = __float2bfloat16(hreg[j]);
            bf16 hl_ = __float2bfloat16(hreg[j] - __bfloat162float(hh));
            g_hbf[dir][np][0][(size_t)bb * HH + hid] = hh;
            g_hbf[dir][np][1][(size_t)bb * HH + hid] = hl_;
            if (p == SS - 1) g_hT[dir][0][hid * BB + bb] = hreg[j];
        }

        __syncthreads();
        if (tid == 0) { __threadfence(); atomicAdd(&g_bar, 1u); }
        ++epoch;

        // barrier shadow: hs0 scatter + next-step prefetch
        if (STORE_HS) {
            #pragma unroll
            for (int j = 0; j < 4; j++)
                g_hs0[dir][((size_t)bb * SS + t) * HH + h0 + hbase + 2 * j] = hreg[j];
        }
        if (p + 1 < SS) {
            int t2 = dir ? (SS - 2 - p) : (p + 1);
            msk = text[(size_t)bb * SS + t2];
            const float* xp = xz + ((size_t)bb * SS + t2) * GG + h0;
            #pragma unroll
            for (int j = 0; j < 4; j++)
                #pragma unroll
                for (int gt = 0; gt < 4; gt++)
                    xzr[j][gt] = xp[gt * HH + hbase + 2 * j];
        }
        if (tid == 0) {
            unsigned tgt = epoch * NBLK;
            while (*(volatile unsigned*)&g_bar < tgt) __nanosleep(32);
            __threadfence();
        }
        __syncthreads();
    }
}

// ---------------- dense head ------------------------------------------------
__global__ void k_dense0(const float* __restrict__ w, const float* __restrict__ bia) {
    int gw = (blockIdx.x * blockDim.x + threadIdx.x) >> 5;
    int lane = threadIdx.x & 31;
    if (gw >= BB * 512) return;
    int b = gw >> 9, j = gw & 511;
    float s = 0.f;
    for (int k = lane; k < KC; k += 32) {
        float a = (k < HH) ? g_hT[0][0][k * BB + b]
                           : g_hT[1][0][(k - HH) * BB + b];
        s += a * w[(size_t)k * 512 + j];
    }
    #pragma unroll
    for (int o = 16; o; o >>= 1) s += __shfl_xor_sync(0xffffffffu, s, o);
    if (!lane) {
        s += bia[j];
        g_fc1[b * 512 + j] = (s >= 0.f) ? s : 0.2f * s;
    }
}

__global__ void k_dense1(const float* __restrict__ w, const float* __restrict__ bia) {
    int gw = (blockIdx.x * blockDim.x + threadIdx.x) >> 5;
    int lane = threadIdx.x & 31;
    if (gw >= BB * 256) return;
    int b = gw >> 8, j = gw & 255;
    float s = 0.f;
    for (int k = lane; k < 512; k += 32)
        s += g_fc1[b * 512 + k] * w[(size_t)k * 256 + j];
    #pragma unroll
    for (int o = 16; o; o >>= 1) s += __shfl_xor_sync(0xffffffffu, s, o);
    if (!lane) {
        s += bia[j];
        g_fc2[b * 256 + j] = (s >= 0.f) ? s : 0.2f * s;
    }
}

__global__ void k_dense2(const float* __restrict__ w, const float* __restrict__ bia,
                         float* __restrict__ out) {
    int b = blockIdx.x;
    int lane = threadIdx.x;
    float s = 0.f;
    for (int k = lane; k < 256; k += 32)
        s += g_fc2[b * 256 + k] * w[k];
    #pragma unroll
    for (int o = 16; o; o >>= 1) s += __shfl_xor_sync(0xffffffffu, s, o);
    if (!lane) out[b] = s + bia[0];
}

// ---------------- launch ----------------------------------------------------
extern "C" void kernel_launch(void* const* d_in, const int* in_sizes, int n_in,
                              void* d_out, int out_size) {
    const int*   text = (const int*)  d_in[0];
    const float* emb  = (const float*)d_in[1];
    const float* W0f  = (const float*)d_in[2];
    const float* U0f  = (const float*)d_in[3];
    const float* b0f  = (const float*)d_in[4];
    const float* W0b  = (const float*)d_in[5];
    const float* U0b  = (const float*)d_in[6];
    const float* b0b  = (const float*)d_in[7];
    const float* W1f  = (const float*)d_in[8];
    const float* U1f  = (const float*)d_in[9];
    const float* b1f  = (const float*)d_in[10];
    const float* W1b  = (const float*)d_in[11];
    const float* U1b  = (const float*)d_in[12];
    const float* b1b  = (const float*)d_in[13];
    const float* d0w  = (const float*)d_in[14];
    const float* d0b  = (const float*)d_in[15];
    const float* d1w  = (const float*)d_in[16];
    const float* d1b  = (const float*)d_in[17];
    const float* d2w  = (const float*)d_in[18];
    const float* d2b  = (const float*)d_in[19];
    float* out = (float*)d_out;

    cudaFuncSetAttribute(k_lstm_mma<true>,
                         cudaFuncAttributeMaxDynamicSharedMemorySize, LSTM_SMEM);
    cudaFuncSetAttribute(k_lstm_mma<false>,
                         cudaFuncAttributeMaxDynamicSharedMemorySize, LSTM_SMEM);
    cudaFuncSetAttribute(k_gemm_tc<0>,
                         cudaFuncAttributeMaxDynamicSharedMemorySize, GEMM_SMEM);
    cudaFuncSetAttribute(k_gemm_tc<1>,
                         cudaFuncAttributeMaxDynamicSharedMemorySize, GEMM_SMEM);

    // ---- layer 0 ----  (recurrence at ncu's launch slot 3)
    k_split_a0<<<(BB * SS * KP0) / 256, 256>>>(text, emb);              // 0
    k_split_w<0><<<(2 * GG * KP0) / 256, 256>>>(W0f, W0b);              // 1 (+bar reset)
    k_gemm_tc<0><<<dim3(256, 8, 2), 256, GEMM_SMEM>>>(b0f, b0b);        // 2
    k_lstm_mma<true><<<dim3(64, 2), 128, LSTM_SMEM>>>(text, U0f, U0b);  // 3

    // ---- layer 1 ----
    k_split_a1<<<(BB * SS * KP1) / 256, 256>>>();
    k_split_w<1><<<(2 * GG * KP1) / 256, 256>>>(W1f, W1b);              // (+bar reset)
    k_gemm_tc<1><<<dim3(256, 8, 2), 256, GEMM_SMEM>>>(b1f, b1b);
    k_lstm_mma<false><<<dim3(64, 2), 128, LSTM_SMEM>>>(text, U1f, U1b);

    // ---- dense head ----
    k_dense0<<<(BB * 512 * 32) / 256, 256>>>(d0w, d0b);
    k_dense1<<<(BB * 256 * 32) / 256, 256>>>(d1w, d1b);
    k_dense2<<<BB, 32>>>(d2w, d2b, out);
}